// round 1
// baseline (speedup 1.0000x reference)
#include <cuda_runtime.h>
#include <math.h>

#define NB 8
#define SQL 1024
#define DM 1024
#define NH 16
#define HD 64
#define NTOK (NB*SQL)

// Scratch (no allocations allowed) — 160 MB of __device__ globals.
__device__ float g_ln[NTOK*DM];            // LayerNorm(x), also the residual
__device__ float g_q [NB*NH*SQL*HD];       // [b,h,s,d]
__device__ float g_k [NB*NH*SQL*HD];
__device__ float g_v [NB*NH*SQL*HD];
__device__ float g_ao[NTOK*DM];            // attention output, [b,s,h*d]

// ---------------------------------------------------------------------------
// LayerNorm: one block per token row (1024 elems), 256 threads, float4 IO.
// ---------------------------------------------------------------------------
__global__ __launch_bounds__(256) void ln_kernel(const float* __restrict__ x,
                                                 const float* __restrict__ gamma,
                                                 const float* __restrict__ beta)
{
    int row = blockIdx.x;
    int tid = threadIdx.x;
    float4 v = reinterpret_cast<const float4*>(x + (size_t)row*DM)[tid];
    float s  = v.x+v.y+v.z+v.w;
    float ss = v.x*v.x+v.y*v.y+v.z*v.z+v.w*v.w;
    #pragma unroll
    for (int o=16;o;o>>=1){
        s  += __shfl_xor_sync(0xffffffffu, s,  o);
        ss += __shfl_xor_sync(0xffffffffu, ss, o);
    }
    __shared__ float ws[8], wss[8];
    int wid = tid>>5, lid = tid&31;
    if (lid==0){ ws[wid]=s; wss[wid]=ss; }
    __syncthreads();
    if (tid==0){
        float a=0.f,c=0.f;
        #pragma unroll
        for (int i=0;i<8;i++){ a+=ws[i]; c+=wss[i]; }
        ws[0]=a; wss[0]=c;
    }
    __syncthreads();
    float mean = ws[0]*(1.0f/DM);
    float var  = wss[0]*(1.0f/DM) - mean*mean;
    float rstd = rsqrtf(var + 1e-3f);
    float4 g  = reinterpret_cast<const float4*>(gamma)[tid];
    float4 bt = reinterpret_cast<const float4*>(beta)[tid];
    float4 o;
    o.x = (v.x-mean)*rstd*g.x + bt.x;
    o.y = (v.y-mean)*rstd*g.y + bt.y;
    o.z = (v.z-mean)*rstd*g.z + bt.z;
    o.w = (v.w-mean)*rstd*g.w + bt.w;
    reinterpret_cast<float4*>(g_ln + (size_t)row*DM)[tid] = o;
}

// ---------------------------------------------------------------------------
// QKV GEMM: [8192,1024] @ [1024,3072] (Wq | Wkv), tiled 128x128x8, 8x8/thread.
// Epilogue scatters into q/k/v in [b,h,s,d] layout.
// ---------------------------------------------------------------------------
__global__ __launch_bounds__(256) void gemm_qkv(const float* __restrict__ Wq,
                                                const float* __restrict__ Wkv,
                                                const float* __restrict__ bq,
                                                const float* __restrict__ bkv)
{
    __shared__ float As[8][128];
    __shared__ float Bs[8][128];
    int tid  = threadIdx.x;
    int row0 = blockIdx.y*128;
    int col0 = blockIdx.x*128;      // 0..2944, block fully inside one region
    const float* W; int ldw, wc0; const float* bias;
    if (col0 < 1024){ W=Wq;  ldw=1024; wc0=col0;        bias=bq +col0;        }
    else            { W=Wkv; ldw=2048; wc0=col0-1024;   bias=bkv+(col0-1024); }

    int ty = tid>>4, tx = tid&15;
    float acc[8][8];
    #pragma unroll
    for (int i=0;i<8;i++)
        #pragma unroll
        for (int j=0;j<8;j++) acc[i][j]=0.f;

    int aRow = tid>>1,  aCol = (tid&1)*4;
    int bRow = tid>>5,  bCol = (tid&31)*4;
    const float* Aptr = g_ln + (size_t)(row0+aRow)*DM + aCol;
    const float* Bptr = W + (size_t)bRow*ldw + wc0 + bCol;

    for (int k0=0; k0<DM; k0+=8){
        float4 a4 = *reinterpret_cast<const float4*>(Aptr + k0);
        float4 b4 = *reinterpret_cast<const float4*>(Bptr + (size_t)k0*ldw);
        As[aCol+0][aRow]=a4.x; As[aCol+1][aRow]=a4.y;
        As[aCol+2][aRow]=a4.z; As[aCol+3][aRow]=a4.w;
        *reinterpret_cast<float4*>(&Bs[bRow][bCol]) = b4;
        __syncthreads();
        #pragma unroll
        for (int k=0;k<8;k++){
            float4 a0 = *reinterpret_cast<const float4*>(&As[k][ty*8]);
            float4 a1 = *reinterpret_cast<const float4*>(&As[k][ty*8+4]);
            float4 c0 = *reinterpret_cast<const float4*>(&Bs[k][tx*8]);
            float4 c1 = *reinterpret_cast<const float4*>(&Bs[k][tx*8+4]);
            float am[8]={a0.x,a0.y,a0.z,a0.w,a1.x,a1.y,a1.z,a1.w};
            float bn[8]={c0.x,c0.y,c0.z,c0.w,c1.x,c1.y,c1.z,c1.w};
            #pragma unroll
            for (int i=0;i<8;i++)
                #pragma unroll
                for (int j=0;j<8;j++) acc[i][j] += am[i]*bn[j];
        }
        __syncthreads();
    }

    #pragma unroll
    for (int i=0;i<8;i++){
        int r  = row0 + ty*8 + i;
        int bb = r >> 10, sIdx = r & 1023;
        #pragma unroll
        for (int j=0;j<8;j++){
            int c   = col0 + tx*8 + j;
            float v = acc[i][j] + bias[tx*8+j];
            if (c < 1024){
                int h=c>>6, d=c&63;
                g_q[(((size_t)(bb*NH+h))*SQL + sIdx)*HD + d] = v;
            } else if (c < 2048){
                int cc=c-1024; int h=cc>>6, d=cc&63;
                g_k[(((size_t)(bb*NH+h))*SQL + sIdx)*HD + d] = v;
            } else {
                int cc=c-2048; int h=cc>>6, d=cc&63;
                g_v[(((size_t)(bb*NH+h))*SQL + sIdx)*HD + d] = v;
            }
        }
    }
}

// ---------------------------------------------------------------------------
// Flash-style attention: block = (bh, 128-row q tile), 1 thread = 1 q row.
// K/V streamed in 32-row tiles through smem (warp-broadcast reads).
// Causal + key-length masking via -1e30 (no inf arithmetic).
// ---------------------------------------------------------------------------
__global__ __launch_bounds__(128) void attn_kernel(const int* __restrict__ lens)
{
    int bh  = blockIdx.x;              // b*16 + h
    int qb  = blockIdx.y;
    int b   = bh >> 4;
    int h   = bh & 15;
    int tid = threadIdx.x;
    int qrow = qb*128 + tid;

    const float* qptr = g_q + ((size_t)bh*SQL + qrow)*HD;
    float q[64];
    #pragma unroll
    for (int d=0; d<64; d+=4){
        float4 t = *reinterpret_cast<const float4*>(qptr+d);
        q[d]=t.x; q[d+1]=t.y; q[d+2]=t.z; q[d+3]=t.w;
    }
    float out[64];
    #pragma unroll
    for (int d=0; d<64; d++) out[d]=0.f;
    float m = -1e30f, l = 0.f;

    int len  = lens[b];
    int kmax = min(qb*128+127, len-1);     // max valid key for this block
    int nkb  = (kmax>>5) + 1;

    __shared__ float Ks[32][64];
    __shared__ float Vs[32][64];
    const float* kbase = g_k + (size_t)bh*SQL*HD;
    const float* vbase = g_v + (size_t)bh*SQL*HD;

    for (int kb=0; kb<nkb; kb++){
        int k0 = kb*32;
        __syncthreads();
        #pragma unroll
        for (int u=0; u<4; u++){
            int idx = (tid + u*128)*4;     // 2048 floats per tile
            *reinterpret_cast<float4*>(&Ks[0][0] + idx) =
                *reinterpret_cast<const float4*>(kbase + (size_t)k0*HD + idx);
            *reinterpret_cast<float4*>(&Vs[0][0] + idx) =
                *reinterpret_cast<const float4*>(vbase + (size_t)k0*HD + idx);
        }
        __syncthreads();

        float sc[32];
        #pragma unroll
        for (int j=0;j<32;j++){
            float a0=0.f,a1=0.f,a2=0.f,a3=0.f;
            #pragma unroll
            for (int d=0; d<64; d+=4){
                float4 kv = *reinterpret_cast<const float4*>(&Ks[j][d]);
                a0 += q[d]  *kv.x; a1 += q[d+1]*kv.y;
                a2 += q[d+2]*kv.z; a3 += q[d+3]*kv.w;
            }
            float sv = ((a0+a1)+(a2+a3)) * 0.125f;   // 1/sqrt(64)
            int jj = k0+j;
            sc[j] = (jj<=qrow && jj<len) ? sv : -1e30f;
        }
        float mb = sc[0];
        #pragma unroll
        for (int j=1;j<32;j++) mb = fmaxf(mb, sc[j]);
        float mnew = fmaxf(m, mb);
        float corr = __expf(m - mnew);
        m = mnew;
        float lsum = 0.f;
        #pragma unroll
        for (int j=0;j<32;j++){ sc[j] = __expf(sc[j]-mnew); lsum += sc[j]; }
        l = l*corr + lsum;
        #pragma unroll
        for (int d=0; d<64; d++) out[d] *= corr;
        #pragma unroll
        for (int j=0;j<32;j++){
            float pj = sc[j];
            #pragma unroll
            for (int d=0; d<64; d+=4){
                float4 vv = *reinterpret_cast<const float4*>(&Vs[j][d]);
                out[d]   += pj*vv.x;
                out[d+1] += pj*vv.y;
                out[d+2] += pj*vv.z;
                out[d+3] += pj*vv.w;
            }
        }
    }

    float inv = 1.f/l;
    float* optr = g_ao + ((size_t)(b*SQL + qrow))*DM + h*HD;
    #pragma unroll
    for (int d=0; d<64; d+=4){
        float4 o;
        o.x=out[d]*inv; o.y=out[d+1]*inv; o.z=out[d+2]*inv; o.w=out[d+3]*inv;
        *reinterpret_cast<float4*>(optr+d) = o;
    }
}

// ---------------------------------------------------------------------------
// Output GEMM: g_ao[8192,1024] @ Wo[1024,1024] + bo + residual(g_ln) -> out
// ---------------------------------------------------------------------------
__global__ __launch_bounds__(256) void gemm_out(const float* __restrict__ Wo,
                                                const float* __restrict__ bo,
                                                float* __restrict__ out)
{
    __shared__ float As[8][128];
    __shared__ float Bs[8][128];
    int tid  = threadIdx.x;
    int row0 = blockIdx.y*128;
    int col0 = blockIdx.x*128;

    int ty = tid>>4, tx = tid&15;
    float acc[8][8];
    #pragma unroll
    for (int i=0;i<8;i++)
        #pragma unroll
        for (int j=0;j<8;j++) acc[i][j]=0.f;

    int aRow = tid>>1,  aCol = (tid&1)*4;
    int bRow = tid>>5,  bCol = (tid&31)*4;
    const float* Aptr = g_ao + (size_t)(row0+aRow)*DM + aCol;
    const float* Bptr = Wo + (size_t)bRow*DM + col0 + bCol;

    for (int k0=0; k0<DM; k0+=8){
        float4 a4 = *reinterpret_cast<const float4*>(Aptr + k0);
        float4 b4 = *reinterpret_cast<const float4*>(Bptr + (size_t)k0*DM);
        As[aCol+0][aRow]=a4.x; As[aCol+1][aRow]=a4.y;
        As[aCol+2][aRow]=a4.z; As[aCol+3][aRow]=a4.w;
        *reinterpret_cast<float4*>(&Bs[bRow][bCol]) = b4;
        __syncthreads();
        #pragma unroll
        for (int k=0;k<8;k++){
            float4 a0 = *reinterpret_cast<const float4*>(&As[k][ty*8]);
            float4 a1 = *reinterpret_cast<const float4*>(&As[k][ty*8+4]);
            float4 c0 = *reinterpret_cast<const float4*>(&Bs[k][tx*8]);
            float4 c1 = *reinterpret_cast<const float4*>(&Bs[k][tx*8+4]);
            float am[8]={a0.x,a0.y,a0.z,a0.w,a1.x,a1.y,a1.z,a1.w};
            float bn[8]={c0.x,c0.y,c0.z,c0.w,c1.x,c1.y,c1.z,c1.w};
            #pragma unroll
            for (int i=0;i<8;i++)
                #pragma unroll
                for (int j=0;j<8;j++) acc[i][j] += am[i]*bn[j];
        }
        __syncthreads();
    }

    #pragma unroll
    for (int i=0;i<8;i++){
        int r = row0 + ty*8 + i;
        #pragma unroll
        for (int j=0;j<8;j++){
            int c = col0 + tx*8 + j;
            out[(size_t)r*DM + c] = acc[i][j] + bo[c] + g_ln[(size_t)r*DM + c];
        }
    }
}

// ---------------------------------------------------------------------------
extern "C" void kernel_launch(void* const* d_in, const int* in_sizes, int n_in,
                              void* d_out, int out_size)
{
    const float* x     = (const float*)d_in[0];
    const int*   lens  = (const int*)  d_in[2];
    const float* Wq    = (const float*)d_in[3];
    const float* bq    = (const float*)d_in[4];
    const float* Wkv   = (const float*)d_in[5];
    const float* bkv   = (const float*)d_in[6];
    const float* Wo    = (const float*)d_in[7];
    const float* bo    = (const float*)d_in[8];
    const float* gamma = (const float*)d_in[9];
    const float* beta  = (const float*)d_in[10];
    float* out = (float*)d_out;

    ln_kernel <<<NTOK, 256>>>(x, gamma, beta);
    gemm_qkv  <<<dim3(24,64), 256>>>(Wq, Wkv, bq, bkv);
    attn_kernel<<<dim3(128,8), 128>>>(lens);
    gemm_out  <<<dim3(8,64), 256>>>(Wo, bo, out);
}

// round 2
// speedup vs baseline: 1.6772x; 1.6772x over previous
#include <cuda_runtime.h>
#include <math.h>

#define NB 8
#define SQL 1024
#define DM 1024
#define NH 16
#define HD 64
#define NTOK (NB*SQL)

// Scratch (no allocations allowed) — __device__ globals.
__device__ float g_ln[NTOK*DM];            // LayerNorm(x), also the residual
__device__ float g_q [NB*NH*SQL*HD];       // [b,h,s,d]
__device__ float g_k [NB*NH*SQL*HD];
__device__ float g_v [NB*NH*SQL*HD];
__device__ float g_ao[NTOK*DM];            // attention output, [b,s,h*d]

// ---------------------------------------------------------------------------
// LayerNorm: one block per token row (1024 elems), 256 threads, float4 IO.
// ---------------------------------------------------------------------------
__global__ __launch_bounds__(256) void ln_kernel(const float* __restrict__ x,
                                                 const float* __restrict__ gamma,
                                                 const float* __restrict__ beta)
{
    int row = blockIdx.x;
    int tid = threadIdx.x;
    float4 v = reinterpret_cast<const float4*>(x + (size_t)row*DM)[tid];
    float s  = v.x+v.y+v.z+v.w;
    float ss = v.x*v.x+v.y*v.y+v.z*v.z+v.w*v.w;
    #pragma unroll
    for (int o=16;o;o>>=1){
        s  += __shfl_xor_sync(0xffffffffu, s,  o);
        ss += __shfl_xor_sync(0xffffffffu, ss, o);
    }
    __shared__ float ws[8], wss[8];
    int wid = tid>>5, lid = tid&31;
    if (lid==0){ ws[wid]=s; wss[wid]=ss; }
    __syncthreads();
    if (tid==0){
        float a=0.f,c=0.f;
        #pragma unroll
        for (int i=0;i<8;i++){ a+=ws[i]; c+=wss[i]; }
        ws[0]=a; wss[0]=c;
    }
    __syncthreads();
    float mean = ws[0]*(1.0f/DM);
    float var  = wss[0]*(1.0f/DM) - mean*mean;
    float rstd = rsqrtf(var + 1e-3f);
    float4 g  = reinterpret_cast<const float4*>(gamma)[tid];
    float4 bt = reinterpret_cast<const float4*>(beta)[tid];
    float4 o;
    o.x = (v.x-mean)*rstd*g.x + bt.x;
    o.y = (v.y-mean)*rstd*g.y + bt.y;
    o.z = (v.z-mean)*rstd*g.z + bt.z;
    o.w = (v.w-mean)*rstd*g.w + bt.w;
    reinterpret_cast<float4*>(g_ln + (size_t)row*DM)[tid] = o;
}

// ---------------------------------------------------------------------------
// tf32 tensor-core GEMM: C[8192, N] = A[8192,1024] @ W[1024, N]
// 128x128x32 tiles, 256 threads (8 warps, 2x4), warp tile 64x32,
// mma.sync.m16n8k8.tf32, double-buffered smem, reg-staged global pipeline.
// MODE 0: A=g_ln, scatter Q.  MODE 1: A=g_ln, scatter K/V.  MODE 2: A=g_ao, out+bias+residual.
// ---------------------------------------------------------------------------
#define BKT 32
#define PADW 136
#define TILE_U (BKT*PADW)           // uints per smem tile
#define GEMM_SMEM (4*TILE_U*4)      // bytes (A0,A1,B0,B1)

__device__ __forceinline__ unsigned f2tf(float f){
    unsigned u; asm("cvt.rna.tf32.f32 %0, %1;" : "=r"(u) : "f"(f)); return u;
}

__device__ __forceinline__ void mma_tf32(float* c, const unsigned* a, const unsigned* b){
    asm volatile(
        "mma.sync.aligned.m16n8k8.row.col.f32.tf32.tf32.f32 "
        "{%0,%1,%2,%3}, {%4,%5,%6,%7}, {%8,%9}, {%0,%1,%2,%3};\n"
        : "+f"(c[0]), "+f"(c[1]), "+f"(c[2]), "+f"(c[3])
        : "r"(a[0]), "r"(a[1]), "r"(a[2]), "r"(a[3]), "r"(b[0]), "r"(b[1]));
}

template<int MODE>
__global__ __launch_bounds__(256) void gemm_tc(const float* __restrict__ Wg,
                                               int ldw,
                                               const float* __restrict__ bias,
                                               float* __restrict__ Cout)
{
    extern __shared__ unsigned smu[];
    const float* Aptr = (MODE==2) ? g_ao : g_ln;

    int tid  = threadIdx.x;
    int lane = tid & 31;
    int warp = tid >> 5;
    int wm = warp >> 2, wn = warp & 3;      // 2 x 4 warp grid
    int row0 = blockIdx.y * 128;
    int col0 = blockIdx.x * 128;

    float acc[4][4][4];
    #pragma unroll
    for (int i=0;i<4;i++)
        #pragma unroll
        for (int j=0;j<4;j++)
            #pragma unroll
            for (int e=0;e<4;e++) acc[i][j][e]=0.f;

    // per-thread load coords
    //  A: id -> m = id>>3 (0..127), k4 = (id&7)*4
    //  B: id -> k = id>>5 (0..31),  n4 = (id&31)*4
    float4 aR[4], bR[4];

    // ---- prologue: tile 0
    {
        #pragma unroll
        for (int i=0;i<4;i++){
            int id = tid + i*256;
            aR[i] = *reinterpret_cast<const float4*>(
                        Aptr + (size_t)(row0 + (id>>3))*DM + (id&7)*4);
            bR[i] = *reinterpret_cast<const float4*>(
                        Wg + (size_t)(id>>5)*ldw + col0 + (id&31)*4);
        }
        unsigned* Adst = smu;                 // buf 0
        unsigned* Bdst = smu + 2*TILE_U;
        #pragma unroll
        for (int i=0;i<4;i++){
            int id = tid + i*256;
            int m = id>>3, k4 = (id&7)*4;
            Adst[(k4+0)*PADW + m] = f2tf(aR[i].x);
            Adst[(k4+1)*PADW + m] = f2tf(aR[i].y);
            Adst[(k4+2)*PADW + m] = f2tf(aR[i].z);
            Adst[(k4+3)*PADW + m] = f2tf(aR[i].w);
            int k = id>>5, n4 = (id&31)*4;
            uint4 bu = { f2tf(bR[i].x), f2tf(bR[i].y), f2tf(bR[i].z), f2tf(bR[i].w) };
            *reinterpret_cast<uint4*>(&Bdst[k*PADW + n4]) = bu;
        }
    }
    __syncthreads();

    int buf = 0;
    const int NKT = DM / BKT;    // 32
    for (int kt = 0; kt < NKT; kt++){
        if (kt+1 < NKT){
            int k0 = (kt+1)*BKT;
            #pragma unroll
            for (int i=0;i<4;i++){
                int id = tid + i*256;
                aR[i] = *reinterpret_cast<const float4*>(
                            Aptr + (size_t)(row0 + (id>>3))*DM + k0 + (id&7)*4);
                bR[i] = *reinterpret_cast<const float4*>(
                            Wg + (size_t)(k0 + (id>>5))*ldw + col0 + (id&31)*4);
            }
        }

        const unsigned* Acur = smu + buf*TILE_U;
        const unsigned* Bcur = smu + 2*TILE_U + buf*TILE_U;
        #pragma unroll
        for (int ks=0; ks<4; ks++){
            int k8 = ks*8;
            unsigned afr[4][4], bfr[4][2];
            #pragma unroll
            for (int mf=0; mf<4; mf++){
                int m0 = wm*64 + mf*16 + (lane>>2);
                afr[mf][0] = Acur[(k8 +   (lane&3))*PADW + m0];
                afr[mf][1] = Acur[(k8 +   (lane&3))*PADW + m0 + 8];
                afr[mf][2] = Acur[(k8+4 + (lane&3))*PADW + m0];
                afr[mf][3] = Acur[(k8+4 + (lane&3))*PADW + m0 + 8];
            }
            #pragma unroll
            for (int nf=0; nf<4; nf++){
                int n0 = wn*32 + nf*8 + (lane>>2);
                bfr[nf][0] = Bcur[(k8 +   (lane&3))*PADW + n0];
                bfr[nf][1] = Bcur[(k8+4 + (lane&3))*PADW + n0];
            }
            #pragma unroll
            for (int mf=0; mf<4; mf++)
                #pragma unroll
                for (int nf=0; nf<4; nf++)
                    mma_tf32(acc[mf][nf], afr[mf], bfr[nf]);
        }

        if (kt+1 < NKT){
            unsigned* Adst = smu + (buf^1)*TILE_U;
            unsigned* Bdst = smu + 2*TILE_U + (buf^1)*TILE_U;
            #pragma unroll
            for (int i=0;i<4;i++){
                int id = tid + i*256;
                int m = id>>3, k4 = (id&7)*4;
                Adst[(k4+0)*PADW + m] = f2tf(aR[i].x);
                Adst[(k4+1)*PADW + m] = f2tf(aR[i].y);
                Adst[(k4+2)*PADW + m] = f2tf(aR[i].z);
                Adst[(k4+3)*PADW + m] = f2tf(aR[i].w);
                int k = id>>5, n4 = (id&31)*4;
                uint4 bu = { f2tf(bR[i].x), f2tf(bR[i].y), f2tf(bR[i].z), f2tf(bR[i].w) };
                *reinterpret_cast<uint4*>(&Bdst[k*PADW + n4]) = bu;
            }
            __syncthreads();
            buf ^= 1;
        }
    }

    // ---- epilogue
    #pragma unroll
    for (int mf=0; mf<4; mf++){
        #pragma unroll
        for (int nf=0; nf<4; nf++){
            #pragma unroll
            for (int e=0; e<4; e++){
                int r = row0 + wm*64 + mf*16 + (lane>>2) + ((e>=2)?8:0);
                int c = col0 + wn*32 + nf*8 + 2*(lane&3) + (e&1);
                float v = acc[mf][nf][e];
                if (MODE == 2){
                    Cout[(size_t)r*DM + c] = v + bias[c] + g_ln[(size_t)r*DM + c];
                } else {
                    v += bias[c];
                    int bb = r >> 10, sIdx = r & 1023;
                    if (MODE == 0){
                        int h = c>>6, d = c&63;
                        g_q[(((size_t)(bb*NH+h))*SQL + sIdx)*HD + d] = v;
                    } else {
                        if (c < 1024){
                            int h = c>>6, d = c&63;
                            g_k[(((size_t)(bb*NH+h))*SQL + sIdx)*HD + d] = v;
                        } else {
                            int cc = c-1024; int h = cc>>6, d = cc&63;
                            g_v[(((size_t)(bb*NH+h))*SQL + sIdx)*HD + d] = v;
                        }
                    }
                }
            }
        }
    }
}

// ---------------------------------------------------------------------------
// Flash-style attention: block = (bh, 128-row q tile), 1 thread = 1 q row.
// ---------------------------------------------------------------------------
__global__ __launch_bounds__(128) void attn_kernel(const int* __restrict__ lens)
{
    int bh  = blockIdx.x;
    int qb  = blockIdx.y;
    int b   = bh >> 4;
    int h   = bh & 15;
    int tid = threadIdx.x;
    int qrow = qb*128 + tid;

    const float* qptr = g_q + ((size_t)bh*SQL + qrow)*HD;
    float q[64];
    #pragma unroll
    for (int d=0; d<64; d+=4){
        float4 t = *reinterpret_cast<const float4*>(qptr+d);
        q[d]=t.x; q[d+1]=t.y; q[d+2]=t.z; q[d+3]=t.w;
    }
    float out[64];
    #pragma unroll
    for (int d=0; d<64; d++) out[d]=0.f;
    float m = -1e30f, l = 0.f;

    int len  = lens[b];
    int kmax = min(qb*128+127, len-1);
    int nkb  = (kmax>>5) + 1;

    __shared__ float Ks[32][64];
    __shared__ float Vs[32][64];
    const float* kbase = g_k + (size_t)bh*SQL*HD;
    const float* vbase = g_v + (size_t)bh*SQL*HD;

    for (int kb=0; kb<nkb; kb++){
        int k0 = kb*32;
        __syncthreads();
        #pragma unroll
        for (int u=0; u<4; u++){
            int idx = (tid + u*128)*4;
            *reinterpret_cast<float4*>(&Ks[0][0] + idx) =
                *reinterpret_cast<const float4*>(kbase + (size_t)k0*HD + idx);
            *reinterpret_cast<float4*>(&Vs[0][0] + idx) =
                *reinterpret_cast<const float4*>(vbase + (size_t)k0*HD + idx);
        }
        __syncthreads();

        float sc[32];
        #pragma unroll
        for (int j=0;j<32;j++){
            float a0=0.f,a1=0.f,a2=0.f,a3=0.f;
            #pragma unroll
            for (int d=0; d<64; d+=4){
                float4 kv = *reinterpret_cast<const float4*>(&Ks[j][d]);
                a0 += q[d]  *kv.x; a1 += q[d+1]*kv.y;
                a2 += q[d+2]*kv.z; a3 += q[d+3]*kv.w;
            }
            float sv = ((a0+a1)+(a2+a3)) * 0.125f;
            int jj = k0+j;
            sc[j] = (jj<=qrow && jj<len) ? sv : -1e30f;
        }
        float mb = sc[0];
        #pragma unroll
        for (int j=1;j<32;j++) mb = fmaxf(mb, sc[j]);
        float mnew = fmaxf(m, mb);
        float corr = __expf(m - mnew);
        m = mnew;
        float lsum = 0.f;
        #pragma unroll
        for (int j=0;j<32;j++){ sc[j] = __expf(sc[j]-mnew); lsum += sc[j]; }
        l = l*corr + lsum;
        #pragma unroll
        for (int d=0; d<64; d++) out[d] *= corr;
        #pragma unroll
        for (int j=0;j<32;j++){
            float pj = sc[j];
            #pragma unroll
            for (int d=0; d<64; d+=4){
                float4 vv = *reinterpret_cast<const float4*>(&Vs[j][d]);
                out[d]   += pj*vv.x;
                out[d+1] += pj*vv.y;
                out[d+2] += pj*vv.z;
                out[d+3] += pj*vv.w;
            }
        }
    }

    float inv = 1.f/l;
    float* optr = g_ao + ((size_t)(b*SQL + qrow))*DM + h*HD;
    #pragma unroll
    for (int d=0; d<64; d+=4){
        float4 o;
        o.x=out[d]*inv; o.y=out[d+1]*inv; o.z=out[d+2]*inv; o.w=out[d+3]*inv;
        *reinterpret_cast<float4*>(optr+d) = o;
    }
}

// ---------------------------------------------------------------------------
extern "C" void kernel_launch(void* const* d_in, const int* in_sizes, int n_in,
                              void* d_out, int out_size)
{
    const float* x     = (const float*)d_in[0];
    const int*   lens  = (const int*)  d_in[2];
    const float* Wq    = (const float*)d_in[3];
    const float* bq    = (const float*)d_in[4];
    const float* Wkv   = (const float*)d_in[5];
    const float* bkv   = (const float*)d_in[6];
    const float* Wo    = (const float*)d_in[7];
    const float* bo    = (const float*)d_in[8];
    const float* gamma = (const float*)d_in[9];
    const float* beta  = (const float*)d_in[10];
    float* out = (float*)d_out;

    static bool attr_done = false;
    if (!attr_done){
        cudaFuncSetAttribute(gemm_tc<0>, cudaFuncAttributeMaxDynamicSharedMemorySize, GEMM_SMEM);
        cudaFuncSetAttribute(gemm_tc<1>, cudaFuncAttributeMaxDynamicSharedMemorySize, GEMM_SMEM);
        cudaFuncSetAttribute(gemm_tc<2>, cudaFuncAttributeMaxDynamicSharedMemorySize, GEMM_SMEM);
        attr_done = true;
    }

    ln_kernel <<<NTOK, 256>>>(x, gamma, beta);
    gemm_tc<0><<<dim3(8, 64), 256, GEMM_SMEM>>>(Wq,  1024, bq,  nullptr);
    gemm_tc<1><<<dim3(16,64), 256, GEMM_SMEM>>>(Wkv, 2048, bkv, nullptr);
    attn_kernel<<<dim3(128,8), 128>>>(lens);
    gemm_tc<2><<<dim3(8, 64), 256, GEMM_SMEM>>>(Wo,  1024, bo,  out);
}

// round 3
// speedup vs baseline: 2.7158x; 1.6192x over previous
#include <cuda_runtime.h>
#include <math.h>

#define NB 8
#define SQL 1024
#define DM 1024
#define NH 16
#define HD 64
#define NTOK (NB*SQL)

// Scratch (no allocations allowed) — __device__ globals.
__device__ float g_ln[NTOK*DM];            // LayerNorm(x), also the residual
__device__ float g_q [NB*NH*SQL*HD];       // [b,h,s,d]
__device__ float g_k [NB*NH*SQL*HD];
__device__ float g_v [NB*NH*SQL*HD];
__device__ float g_ao[NTOK*DM];            // attention output, [b,s,h*d]

__device__ __forceinline__ unsigned f2tf(float f){
    unsigned u; asm("cvt.rna.tf32.f32 %0, %1;" : "=r"(u) : "f"(f)); return u;
}

__device__ __forceinline__ void mma_tf32(float* c, const unsigned* a, const unsigned* b){
    asm volatile(
        "mma.sync.aligned.m16n8k8.row.col.f32.tf32.tf32.f32 "
        "{%0,%1,%2,%3}, {%4,%5,%6,%7}, {%8,%9}, {%0,%1,%2,%3};\n"
        : "+f"(c[0]), "+f"(c[1]), "+f"(c[2]), "+f"(c[3])
        : "r"(a[0]), "r"(a[1]), "r"(a[2]), "r"(a[3]), "r"(b[0]), "r"(b[1]));
}

// ---------------------------------------------------------------------------
// LayerNorm: one block per token row (1024 elems), 256 threads, float4 IO.
// ---------------------------------------------------------------------------
__global__ __launch_bounds__(256) void ln_kernel(const float* __restrict__ x,
                                                 const float* __restrict__ gamma,
                                                 const float* __restrict__ beta)
{
    int row = blockIdx.x;
    int tid = threadIdx.x;
    float4 v = reinterpret_cast<const float4*>(x + (size_t)row*DM)[tid];
    float s  = v.x+v.y+v.z+v.w;
    float ss = v.x*v.x+v.y*v.y+v.z*v.z+v.w*v.w;
    #pragma unroll
    for (int o=16;o;o>>=1){
        s  += __shfl_xor_sync(0xffffffffu, s,  o);
        ss += __shfl_xor_sync(0xffffffffu, ss, o);
    }
    __shared__ float ws[8], wss[8];
    int wid = tid>>5, lid = tid&31;
    if (lid==0){ ws[wid]=s; wss[wid]=ss; }
    __syncthreads();
    if (tid==0){
        float a=0.f,c=0.f;
        #pragma unroll
        for (int i=0;i<8;i++){ a+=ws[i]; c+=wss[i]; }
        ws[0]=a; wss[0]=c;
    }
    __syncthreads();
    float mean = ws[0]*(1.0f/DM);
    float var  = wss[0]*(1.0f/DM) - mean*mean;
    float rstd = rsqrtf(var + 1e-3f);
    float4 g  = reinterpret_cast<const float4*>(gamma)[tid];
    float4 bt = reinterpret_cast<const float4*>(beta)[tid];
    float4 o;
    o.x = (v.x-mean)*rstd*g.x + bt.x;
    o.y = (v.y-mean)*rstd*g.y + bt.y;
    o.z = (v.z-mean)*rstd*g.z + bt.z;
    o.w = (v.w-mean)*rstd*g.w + bt.w;
    reinterpret_cast<float4*>(g_ln + (size_t)row*DM)[tid] = o;
}

// ---------------------------------------------------------------------------
// tf32 tensor-core GEMM (unchanged from round 2).
// ---------------------------------------------------------------------------
#define BKT 32
#define PADW 136
#define TILE_U (BKT*PADW)
#define GEMM_SMEM (4*TILE_U*4)

template<int MODE>
__global__ __launch_bounds__(256) void gemm_tc(const float* __restrict__ Wg,
                                               int ldw,
                                               const float* __restrict__ bias,
                                               float* __restrict__ Cout)
{
    extern __shared__ unsigned smu[];
    const float* Aptr = (MODE==2) ? g_ao : g_ln;

    int tid  = threadIdx.x;
    int lane = tid & 31;
    int warp = tid >> 5;
    int wm = warp >> 2, wn = warp & 3;
    int row0 = blockIdx.y * 128;
    int col0 = blockIdx.x * 128;

    float acc[4][4][4];
    #pragma unroll
    for (int i=0;i<4;i++)
        #pragma unroll
        for (int j=0;j<4;j++)
            #pragma unroll
            for (int e=0;e<4;e++) acc[i][j][e]=0.f;

    float4 aR[4], bR[4];
    {
        #pragma unroll
        for (int i=0;i<4;i++){
            int id = tid + i*256;
            aR[i] = *reinterpret_cast<const float4*>(
                        Aptr + (size_t)(row0 + (id>>3))*DM + (id&7)*4);
            bR[i] = *reinterpret_cast<const float4*>(
                        Wg + (size_t)(id>>5)*ldw + col0 + (id&31)*4);
        }
        unsigned* Adst = smu;
        unsigned* Bdst = smu + 2*TILE_U;
        #pragma unroll
        for (int i=0;i<4;i++){
            int id = tid + i*256;
            int m = id>>3, k4 = (id&7)*4;
            Adst[(k4+0)*PADW + m] = f2tf(aR[i].x);
            Adst[(k4+1)*PADW + m] = f2tf(aR[i].y);
            Adst[(k4+2)*PADW + m] = f2tf(aR[i].z);
            Adst[(k4+3)*PADW + m] = f2tf(aR[i].w);
            int k = id>>5, n4 = (id&31)*4;
            uint4 bu = { f2tf(bR[i].x), f2tf(bR[i].y), f2tf(bR[i].z), f2tf(bR[i].w) };
            *reinterpret_cast<uint4*>(&Bdst[k*PADW + n4]) = bu;
        }
    }
    __syncthreads();

    int buf = 0;
    const int NKT = DM / BKT;
    for (int kt = 0; kt < NKT; kt++){
        if (kt+1 < NKT){
            int k0 = (kt+1)*BKT;
            #pragma unroll
            for (int i=0;i<4;i++){
                int id = tid + i*256;
                aR[i] = *reinterpret_cast<const float4*>(
                            Aptr + (size_t)(row0 + (id>>3))*DM + k0 + (id&7)*4);
                bR[i] = *reinterpret_cast<const float4*>(
                            Wg + (size_t)(k0 + (id>>5))*ldw + col0 + (id&31)*4);
            }
        }

        const unsigned* Acur = smu + buf*TILE_U;
        const unsigned* Bcur = smu + 2*TILE_U + buf*TILE_U;
        #pragma unroll
        for (int ks=0; ks<4; ks++){
            int k8 = ks*8;
            unsigned afr[4][4], bfr[4][2];
            #pragma unroll
            for (int mf=0; mf<4; mf++){
                int m0 = wm*64 + mf*16 + (lane>>2);
                afr[mf][0] = Acur[(k8 +   (lane&3))*PADW + m0];
                afr[mf][1] = Acur[(k8 +   (lane&3))*PADW + m0 + 8];
                afr[mf][2] = Acur[(k8+4 + (lane&3))*PADW + m0];
                afr[mf][3] = Acur[(k8+4 + (lane&3))*PADW + m0 + 8];
            }
            #pragma unroll
            for (int nf=0; nf<4; nf++){
                int n0 = wn*32 + nf*8 + (lane>>2);
                bfr[nf][0] = Bcur[(k8 +   (lane&3))*PADW + n0];
                bfr[nf][1] = Bcur[(k8+4 + (lane&3))*PADW + n0];
            }
            #pragma unroll
            for (int mf=0; mf<4; mf++)
                #pragma unroll
                for (int nf=0; nf<4; nf++)
                    mma_tf32(acc[mf][nf], afr[mf], bfr[nf]);
        }

        if (kt+1 < NKT){
            unsigned* Adst = smu + (buf^1)*TILE_U;
            unsigned* Bdst = smu + 2*TILE_U + (buf^1)*TILE_U;
            #pragma unroll
            for (int i=0;i<4;i++){
                int id = tid + i*256;
                int m = id>>3, k4 = (id&7)*4;
                Adst[(k4+0)*PADW + m] = f2tf(aR[i].x);
                Adst[(k4+1)*PADW + m] = f2tf(aR[i].y);
                Adst[(k4+2)*PADW + m] = f2tf(aR[i].z);
                Adst[(k4+3)*PADW + m] = f2tf(aR[i].w);
                int k = id>>5, n4 = (id&31)*4;
                uint4 bu = { f2tf(bR[i].x), f2tf(bR[i].y), f2tf(bR[i].z), f2tf(bR[i].w) };
                *reinterpret_cast<uint4*>(&Bdst[k*PADW + n4]) = bu;
            }
            __syncthreads();
            buf ^= 1;
        }
    }

    #pragma unroll
    for (int mf=0; mf<4; mf++){
        #pragma unroll
        for (int nf=0; nf<4; nf++){
            #pragma unroll
            for (int e=0; e<4; e++){
                int r = row0 + wm*64 + mf*16 + (lane>>2) + ((e>=2)?8:0);
                int c = col0 + wn*32 + nf*8 + 2*(lane&3) + (e&1);
                float v = acc[mf][nf][e];
                if (MODE == 2){
                    Cout[(size_t)r*DM + c] = v + bias[c] + g_ln[(size_t)r*DM + c];
                } else {
                    v += bias[c];
                    int bb = r >> 10, sIdx = r & 1023;
                    if (MODE == 0){
                        int h = c>>6, d = c&63;
                        g_q[(((size_t)(bb*NH+h))*SQL + sIdx)*HD + d] = v;
                    } else {
                        if (c < 1024){
                            int h = c>>6, d = c&63;
                            g_k[(((size_t)(bb*NH+h))*SQL + sIdx)*HD + d] = v;
                        } else {
                            int cc = c-1024; int h = cc>>6, d = cc&63;
                            g_v[(((size_t)(bb*NH+h))*SQL + sIdx)*HD + d] = v;
                        }
                    }
                }
            }
        }
    }
}

// ---------------------------------------------------------------------------
// Tensor-core flash attention.
// Block = (bh, 128-query tile), 256 threads / 8 warps; warp owns 16 q rows.
// K/V streamed in 64-key tiles; S=QK^T and O+=P*V via mma.m16n8k8.tf32.
// Smem strides chosen for conflict-free fragment access:
//   Ks stride 68, Vs stride 72, Pw (also Q staging) stride 68.
// ---------------------------------------------------------------------------
#define KS_STRIDE 68
#define VS_STRIDE 72
#define PW_STRIDE 68
#define ATT_KS_U  (64*KS_STRIDE)
#define ATT_VS_U  (64*VS_STRIDE)
#define ATT_PW_U  (128*PW_STRIDE)
#define ATT_SMEM  ((ATT_KS_U + ATT_VS_U + ATT_PW_U)*4)

__global__ __launch_bounds__(256) void attn_tc(const int* __restrict__ lens)
{
    extern __shared__ unsigned sm[];
    unsigned* Ks = sm;
    unsigned* Vs = sm + ATT_KS_U;
    unsigned* Pw = sm + ATT_KS_U + ATT_VS_U;   // also used as Q staging

    int bh = blockIdx.x;                // b*16 + h
    int qb = blockIdx.y;
    int b  = bh >> 4;
    int h  = bh & 15;
    int tid  = threadIdx.x;
    int lane = tid & 31;
    int w    = tid >> 5;                // warp 0..7
    int q0   = qb*128;

    const float* qbase = g_q + (size_t)bh*SQL*HD;
    const float* kbase = g_k + (size_t)bh*SQL*HD;
    const float* vbase = g_v + (size_t)bh*SQL*HD;

    // ---- stage Q tile into Pw region (tf32), then pull fragments into regs
    #pragma unroll
    for (int i=0;i<8;i++){
        int id = tid + i*256;
        int row = id>>4, d4 = (id&15)*4;
        float4 t = *reinterpret_cast<const float4*>(qbase + (size_t)(q0+row)*HD + d4);
        uint4 u = { f2tf(t.x), f2tf(t.y), f2tf(t.z), f2tf(t.w) };
        *reinterpret_cast<uint4*>(&Pw[row*PW_STRIDE + d4]) = u;
    }
    __syncthreads();

    unsigned aQ[8][4];
    {
        int m0 = w*16 + (lane>>2);
        #pragma unroll
        for (int ks=0; ks<8; ks++){
            int k = ks*8 + (lane&3);
            aQ[ks][0] = Pw[ m0   *PW_STRIDE + k];
            aQ[ks][1] = Pw[(m0+8)*PW_STRIDE + k];
            aQ[ks][2] = Pw[ m0   *PW_STRIDE + k+4];
            aQ[ks][3] = Pw[(m0+8)*PW_STRIDE + k+4];
        }
    }
    // warp w only reads rows it will later write; cross-warp safety for the
    // Pw-as-P reuse is per-warp private, but make Q staging fully drained:
    __syncthreads();

    int qrow0 = q0 + w*16 + (lane>>2);
    int qrow1 = qrow0 + 8;
    int lr0   = w*16 + (lane>>2);       // local row in Pw

    float Oacc[8][4];
    #pragma unroll
    for (int i=0;i<8;i++)
        #pragma unroll
        for (int e=0;e<4;e++) Oacc[i][e]=0.f;
    float mi0=-1e30f, mi1=-1e30f, li0=0.f, li1=0.f;

    int len  = lens[b];
    int kmax = min(q0+127, len-1);
    int nkb  = (kmax>>6) + 1;

    for (int kb=0; kb<nkb; kb++){
        int k0 = kb*64;
        __syncthreads();
        // load K,V 64x64 tiles (fp32 -> tf32)
        #pragma unroll
        for (int i=0;i<4;i++){
            int id = tid + i*256;
            int kr = id>>4, d4 = (id&15)*4;
            float4 tk = *reinterpret_cast<const float4*>(kbase + (size_t)(k0+kr)*HD + d4);
            float4 tv = *reinterpret_cast<const float4*>(vbase + (size_t)(k0+kr)*HD + d4);
            uint4 uk = { f2tf(tk.x), f2tf(tk.y), f2tf(tk.z), f2tf(tk.w) };
            uint4 uv = { f2tf(tv.x), f2tf(tv.y), f2tf(tv.z), f2tf(tv.w) };
            *reinterpret_cast<uint4*>(&Ks[kr*KS_STRIDE + d4]) = uk;
            *reinterpret_cast<uint4*>(&Vs[kr*VS_STRIDE + d4]) = uv;
        }
        __syncthreads();

        // ---- S = Q K^T  (scores in sc[nf][e])
        float sc[8][4];
        #pragma unroll
        for (int nf=0; nf<8; nf++){
            sc[nf][0]=0.f; sc[nf][1]=0.f; sc[nf][2]=0.f; sc[nf][3]=0.f;
            int n0 = nf*8 + (lane>>2);
            #pragma unroll
            for (int ks=0; ks<8; ks++){
                unsigned bfr[2];
                bfr[0] = Ks[n0*KS_STRIDE + ks*8 +     (lane&3)];
                bfr[1] = Ks[n0*KS_STRIDE + ks*8 + 4 + (lane&3)];
                mma_tf32(sc[nf], aQ[ks], bfr);
            }
        }

        // ---- mask + scale
        #pragma unroll
        for (int nf=0; nf<8; nf++){
            int jc = k0 + nf*8 + 2*(lane&3);
            #pragma unroll
            for (int e=0; e<4; e++){
                int j   = jc + (e&1);
                int row = (e>=2) ? qrow1 : qrow0;
                float v = sc[nf][e]*0.125f;
                sc[nf][e] = (j<=row && j<len) ? v : -1e30f;
            }
        }

        // ---- online softmax
        float rmax0=-1e30f, rmax1=-1e30f;
        #pragma unroll
        for (int nf=0; nf<8; nf++){
            rmax0 = fmaxf(rmax0, fmaxf(sc[nf][0], sc[nf][1]));
            rmax1 = fmaxf(rmax1, fmaxf(sc[nf][2], sc[nf][3]));
        }
        rmax0 = fmaxf(rmax0, __shfl_xor_sync(0xffffffffu, rmax0, 1));
        rmax0 = fmaxf(rmax0, __shfl_xor_sync(0xffffffffu, rmax0, 2));
        rmax1 = fmaxf(rmax1, __shfl_xor_sync(0xffffffffu, rmax1, 1));
        rmax1 = fmaxf(rmax1, __shfl_xor_sync(0xffffffffu, rmax1, 2));

        float mn0 = fmaxf(mi0, rmax0);
        float mn1 = fmaxf(mi1, rmax1);
        float corr0 = __expf(mi0 - mn0);
        float corr1 = __expf(mi1 - mn1);
        mi0 = mn0; mi1 = mn1;

        float rs0=0.f, rs1=0.f;
        #pragma unroll
        for (int nf=0; nf<8; nf++){
            sc[nf][0] = __expf(sc[nf][0]-mn0);
            sc[nf][1] = __expf(sc[nf][1]-mn0);
            sc[nf][2] = __expf(sc[nf][2]-mn1);
            sc[nf][3] = __expf(sc[nf][3]-mn1);
            rs0 += sc[nf][0]+sc[nf][1];
            rs1 += sc[nf][2]+sc[nf][3];
        }
        rs0 += __shfl_xor_sync(0xffffffffu, rs0, 1);
        rs0 += __shfl_xor_sync(0xffffffffu, rs0, 2);
        rs1 += __shfl_xor_sync(0xffffffffu, rs1, 1);
        rs1 += __shfl_xor_sync(0xffffffffu, rs1, 2);
        li0 = li0*corr0 + rs0;
        li1 = li1*corr1 + rs1;

        #pragma unroll
        for (int nf=0; nf<8; nf++){
            Oacc[nf][0]*=corr0; Oacc[nf][1]*=corr0;
            Oacc[nf][2]*=corr1; Oacc[nf][3]*=corr1;
        }

        // ---- P -> warp-private smem rows (tf32)
        #pragma unroll
        for (int nf=0; nf<8; nf++){
            int c = nf*8 + 2*(lane&3);
            uint2 p01 = { f2tf(sc[nf][0]), f2tf(sc[nf][1]) };
            uint2 p23 = { f2tf(sc[nf][2]), f2tf(sc[nf][3]) };
            *reinterpret_cast<uint2*>(&Pw[ lr0   *PW_STRIDE + c]) = p01;
            *reinterpret_cast<uint2*>(&Pw[(lr0+8)*PW_STRIDE + c]) = p23;
        }
        __syncwarp();

        // ---- O += P V
        #pragma unroll
        for (int ks=0; ks<8; ks++){
            unsigned aP[4];
            aP[0] = Pw[ lr0   *PW_STRIDE + ks*8 +     (lane&3)];
            aP[1] = Pw[(lr0+8)*PW_STRIDE + ks*8 +     (lane&3)];
            aP[2] = Pw[ lr0   *PW_STRIDE + ks*8 + 4 + (lane&3)];
            aP[3] = Pw[(lr0+8)*PW_STRIDE + ks*8 + 4 + (lane&3)];
            #pragma unroll
            for (int df=0; df<8; df++){
                unsigned bfr[2];
                bfr[0] = Vs[(ks*8 +     (lane&3))*VS_STRIDE + df*8 + (lane>>2)];
                bfr[1] = Vs[(ks*8 + 4 + (lane&3))*VS_STRIDE + df*8 + (lane>>2)];
                mma_tf32(Oacc[df], aP, bfr);
            }
        }
    }

    // ---- write O / l
    float inv0 = 1.f/li0, inv1 = 1.f/li1;
    float* o0 = g_ao + ((size_t)(b*SQL + qrow0))*DM + h*HD;
    float* o1 = g_ao + ((size_t)(b*SQL + qrow1))*DM + h*HD;
    #pragma unroll
    for (int df=0; df<8; df++){
        int c = df*8 + 2*(lane&3);
        float2 v0 = { Oacc[df][0]*inv0, Oacc[df][1]*inv0 };
        float2 v1 = { Oacc[df][2]*inv1, Oacc[df][3]*inv1 };
        *reinterpret_cast<float2*>(o0 + c) = v0;
        *reinterpret_cast<float2*>(o1 + c) = v1;
    }
}

// ---------------------------------------------------------------------------
extern "C" void kernel_launch(void* const* d_in, const int* in_sizes, int n_in,
                              void* d_out, int out_size)
{
    const float* x     = (const float*)d_in[0];
    const int*   lens  = (const int*)  d_in[2];
    const float* Wq    = (const float*)d_in[3];
    const float* bq    = (const float*)d_in[4];
    const float* Wkv   = (const float*)d_in[5];
    const float* bkv   = (const float*)d_in[6];
    const float* Wo    = (const float*)d_in[7];
    const float* bo    = (const float*)d_in[8];
    const float* gamma = (const float*)d_in[9];
    const float* beta  = (const float*)d_in[10];
    float* out = (float*)d_out;

    cudaFuncSetAttribute(gemm_tc<0>, cudaFuncAttributeMaxDynamicSharedMemorySize, GEMM_SMEM);
    cudaFuncSetAttribute(gemm_tc<1>, cudaFuncAttributeMaxDynamicSharedMemorySize, GEMM_SMEM);
    cudaFuncSetAttribute(gemm_tc<2>, cudaFuncAttributeMaxDynamicSharedMemorySize, GEMM_SMEM);
    cudaFuncSetAttribute(attn_tc,    cudaFuncAttributeMaxDynamicSharedMemorySize, ATT_SMEM);

    ln_kernel <<<NTOK, 256>>>(x, gamma, beta);
    gemm_tc<0><<<dim3(8, 64), 256, GEMM_SMEM>>>(Wq,  1024, bq,  nullptr);
    gemm_tc<1><<<dim3(16,64), 256, GEMM_SMEM>>>(Wkv, 2048, bkv, nullptr);
    attn_tc   <<<dim3(128,8), 256, ATT_SMEM>>>(lens);
    gemm_tc<2><<<dim3(8, 64), 256, GEMM_SMEM>>>(Wo,  1024, bo,  out);
}

// round 4
// speedup vs baseline: 4.6469x; 1.7111x over previous
#include <cuda_runtime.h>
#include <cuda_bf16.h>
#include <math.h>

#define NB 8
#define SQL 1024
#define DM 1024
#define NH 16
#define HD 64
#define NTOK (NB*SQL)

// Scratch (no allocations allowed) — __device__ globals.
__device__ float g_ln[NTOK*DM];            // LayerNorm(x), also the residual
__device__ float g_q [NB*NH*SQL*HD];       // [b,h,s,d]
__device__ float g_k [NB*NH*SQL*HD];
__device__ float g_v [NB*NH*SQL*HD];
__device__ float g_ao[NTOK*DM];            // attention output, [b,s,h*d]

__device__ __forceinline__ unsigned f2tf(float f){
    unsigned u; asm("cvt.rna.tf32.f32 %0, %1;" : "=r"(u) : "f"(f)); return u;
}
__device__ __forceinline__ unsigned packbf(float lo, float hi){
    __nv_bfloat162 h = __floats2bfloat162_rn(lo, hi);
    return *reinterpret_cast<unsigned*>(&h);
}

__device__ __forceinline__ void mma_tf32(float* c, const unsigned* a, const unsigned* b){
    asm volatile(
        "mma.sync.aligned.m16n8k8.row.col.f32.tf32.tf32.f32 "
        "{%0,%1,%2,%3}, {%4,%5,%6,%7}, {%8,%9}, {%0,%1,%2,%3};\n"
        : "+f"(c[0]), "+f"(c[1]), "+f"(c[2]), "+f"(c[3])
        : "r"(a[0]), "r"(a[1]), "r"(a[2]), "r"(a[3]), "r"(b[0]), "r"(b[1]));
}
__device__ __forceinline__ void mma_bf16(float* c, const unsigned* a, const unsigned* b){
    asm volatile(
        "mma.sync.aligned.m16n8k16.row.col.f32.bf16.bf16.f32 "
        "{%0,%1,%2,%3}, {%4,%5,%6,%7}, {%8,%9}, {%0,%1,%2,%3};\n"
        : "+f"(c[0]), "+f"(c[1]), "+f"(c[2]), "+f"(c[3])
        : "r"(a[0]), "r"(a[1]), "r"(a[2]), "r"(a[3]), "r"(b[0]), "r"(b[1]));
}

// ---------------------------------------------------------------------------
// LayerNorm: one block per token row (1024 elems), 256 threads, float4 IO.
// ---------------------------------------------------------------------------
__global__ __launch_bounds__(256) void ln_kernel(const float* __restrict__ x,
                                                 const float* __restrict__ gamma,
                                                 const float* __restrict__ beta)
{
    int row = blockIdx.x;
    int tid = threadIdx.x;
    float4 v = reinterpret_cast<const float4*>(x + (size_t)row*DM)[tid];
    float s  = v.x+v.y+v.z+v.w;
    float ss = v.x*v.x+v.y*v.y+v.z*v.z+v.w*v.w;
    #pragma unroll
    for (int o=16;o;o>>=1){
        s  += __shfl_xor_sync(0xffffffffu, s,  o);
        ss += __shfl_xor_sync(0xffffffffu, ss, o);
    }
    __shared__ float ws[8], wss[8];
    int wid = tid>>5, lid = tid&31;
    if (lid==0){ ws[wid]=s; wss[wid]=ss; }
    __syncthreads();
    if (tid==0){
        float a=0.f,c=0.f;
        #pragma unroll
        for (int i=0;i<8;i++){ a+=ws[i]; c+=wss[i]; }
        ws[0]=a; wss[0]=c;
    }
    __syncthreads();
    float mean = ws[0]*(1.0f/DM);
    float var  = wss[0]*(1.0f/DM) - mean*mean;
    float rstd = rsqrtf(var + 1e-3f);
    float4 g  = reinterpret_cast<const float4*>(gamma)[tid];
    float4 bt = reinterpret_cast<const float4*>(beta)[tid];
    float4 o;
    o.x = (v.x-mean)*rstd*g.x + bt.x;
    o.y = (v.y-mean)*rstd*g.y + bt.y;
    o.z = (v.z-mean)*rstd*g.z + bt.z;
    o.w = (v.w-mean)*rstd*g.w + bt.w;
    reinterpret_cast<float4*>(g_ln + (size_t)row*DM)[tid] = o;
}

// ---------------------------------------------------------------------------
// bf16 tensor-core GEMM: C[8192, N] = A[8192,1024] @ W[1024, N]
// 128x128x32 tiles, 256 threads / 8 warps (2x4), warp tile 64x32,
// mma.m16n8k16.bf16, double-buffered smem, fp32 gmem -> inline bf16 cvt.
// Smem: A as [m][k2] stride 20 (conflict-free frag loads),
//       B as [k2][n] stride 136 (conflict-free frag loads + STS.128 stores).
// MODE 0: A=g_ln, scatter Q.  MODE 1: A=g_ln, scatter K/V.  MODE 2: A=g_ao, out.
// ---------------------------------------------------------------------------
#define BKT   32
#define ASTR  20
#define BSTR  136
#define ATILE_U (128*ASTR)        // 2560 uints
#define BTILE_U (16*BSTR)         // 2176 uints
#define GEMM_SMEM ((2*ATILE_U + 2*BTILE_U)*4)   // 37888 bytes

template<int MODE>
__global__ __launch_bounds__(256) void gemm_bf(const float* __restrict__ Wg,
                                               int ldw,
                                               const float* __restrict__ bias,
                                               float* __restrict__ Cout)
{
    extern __shared__ unsigned smu[];
    const float* Aptr = (MODE==2) ? g_ao : g_ln;

    int tid  = threadIdx.x;
    int lane = tid & 31;
    int warp = tid >> 5;
    int wm = warp >> 2, wn = warp & 3;
    int row0 = blockIdx.y * 128;
    int col0 = blockIdx.x * 128;

    float acc[4][4][4];
    #pragma unroll
    for (int i=0;i<4;i++)
        #pragma unroll
        for (int j=0;j<4;j++)
            #pragma unroll
            for (int e=0;e<4;e++) acc[i][j][e]=0.f;

    float4 aR[4], bRa[2], bRb[2];

    // ---- prologue: load tile 0 into regs, store to buf 0
    {
        #pragma unroll
        for (int i=0;i<4;i++){
            int id = tid + i*256;
            aR[i] = *reinterpret_cast<const float4*>(
                        Aptr + (size_t)(row0 + (id>>3))*DM + (id&7)*4);
        }
        #pragma unroll
        for (int i=0;i<2;i++){
            int k2 = (tid>>5) + i*8;
            int n4 = (tid&31)*4;
            bRa[i] = *reinterpret_cast<const float4*>(Wg + (size_t)(2*k2  )*ldw + col0 + n4);
            bRb[i] = *reinterpret_cast<const float4*>(Wg + (size_t)(2*k2+1)*ldw + col0 + n4);
        }
        unsigned* Ad = smu;
        unsigned* Bd = smu + 2*ATILE_U;
        #pragma unroll
        for (int i=0;i<4;i++){
            int id = tid + i*256;
            int m = id>>3, k2 = (id&7)*2;
            uint2 u = { packbf(aR[i].x, aR[i].y), packbf(aR[i].z, aR[i].w) };
            *reinterpret_cast<uint2*>(&Ad[m*ASTR + k2]) = u;
        }
        #pragma unroll
        for (int i=0;i<2;i++){
            int k2 = (tid>>5) + i*8;
            int n4 = (tid&31)*4;
            uint4 u = { packbf(bRa[i].x, bRb[i].x), packbf(bRa[i].y, bRb[i].y),
                        packbf(bRa[i].z, bRb[i].z), packbf(bRa[i].w, bRb[i].w) };
            *reinterpret_cast<uint4*>(&Bd[k2*BSTR + n4]) = u;
        }
    }
    __syncthreads();

    int buf = 0;
    const int NKT = DM / BKT;    // 32
    for (int kt = 0; kt < NKT; kt++){
        if (kt+1 < NKT){
            int k0 = (kt+1)*BKT;
            #pragma unroll
            for (int i=0;i<4;i++){
                int id = tid + i*256;
                aR[i] = *reinterpret_cast<const float4*>(
                            Aptr + (size_t)(row0 + (id>>3))*DM + k0 + (id&7)*4);
            }
            #pragma unroll
            for (int i=0;i<2;i++){
                int k2 = (tid>>5) + i*8;
                int n4 = (tid&31)*4;
                bRa[i] = *reinterpret_cast<const float4*>(Wg + (size_t)(k0+2*k2  )*ldw + col0 + n4);
                bRb[i] = *reinterpret_cast<const float4*>(Wg + (size_t)(k0+2*k2+1)*ldw + col0 + n4);
            }
        }

        const unsigned* Ac = smu + buf*ATILE_U;
        const unsigned* Bc = smu + 2*ATILE_U + buf*BTILE_U;
        #pragma unroll
        for (int ks=0; ks<2; ks++){
            int kb = ks*8;
            unsigned afr[4][4], bfr[4][2];
            #pragma unroll
            for (int mf=0; mf<4; mf++){
                int m0 = wm*64 + mf*16 + (lane>>2);
                afr[mf][0] = Ac[ m0   *ASTR + kb +     (lane&3)];
                afr[mf][1] = Ac[(m0+8)*ASTR + kb +     (lane&3)];
                afr[mf][2] = Ac[ m0   *ASTR + kb + 4 + (lane&3)];
                afr[mf][3] = Ac[(m0+8)*ASTR + kb + 4 + (lane&3)];
            }
            #pragma unroll
            for (int nf=0; nf<4; nf++){
                int n0 = wn*32 + nf*8 + (lane>>2);
                bfr[nf][0] = Bc[(kb +     (lane&3))*BSTR + n0];
                bfr[nf][1] = Bc[(kb + 4 + (lane&3))*BSTR + n0];
            }
            #pragma unroll
            for (int mf=0; mf<4; mf++)
                #pragma unroll
                for (int nf=0; nf<4; nf++)
                    mma_bf16(acc[mf][nf], afr[mf], bfr[nf]);
        }

        if (kt+1 < NKT){
            unsigned* Ad = smu + (buf^1)*ATILE_U;
            unsigned* Bd = smu + 2*ATILE_U + (buf^1)*BTILE_U;
            #pragma unroll
            for (int i=0;i<4;i++){
                int id = tid + i*256;
                int m = id>>3, k2 = (id&7)*2;
                uint2 u = { packbf(aR[i].x, aR[i].y), packbf(aR[i].z, aR[i].w) };
                *reinterpret_cast<uint2*>(&Ad[m*ASTR + k2]) = u;
            }
            #pragma unroll
            for (int i=0;i<2;i++){
                int k2 = (tid>>5) + i*8;
                int n4 = (tid&31)*4;
                uint4 u = { packbf(bRa[i].x, bRb[i].x), packbf(bRa[i].y, bRb[i].y),
                            packbf(bRa[i].z, bRb[i].z), packbf(bRa[i].w, bRb[i].w) };
                *reinterpret_cast<uint4*>(&Bd[k2*BSTR + n4]) = u;
            }
            __syncthreads();
            buf ^= 1;
        }
    }

    // ---- epilogue (accumulator layout identical to tf32 version)
    #pragma unroll
    for (int mf=0; mf<4; mf++){
        #pragma unroll
        for (int nf=0; nf<4; nf++){
            #pragma unroll
            for (int e=0; e<4; e++){
                int r = row0 + wm*64 + mf*16 + (lane>>2) + ((e>=2)?8:0);
                int c = col0 + wn*32 + nf*8 + 2*(lane&3) + (e&1);
                float v = acc[mf][nf][e];
                if (MODE == 2){
                    Cout[(size_t)r*DM + c] = v + bias[c] + g_ln[(size_t)r*DM + c];
                } else {
                    v += bias[c];
                    int bb = r >> 10, sIdx = r & 1023;
                    if (MODE == 0){
                        int h = c>>6, d = c&63;
                        g_q[(((size_t)(bb*NH+h))*SQL + sIdx)*HD + d] = v;
                    } else {
                        if (c < 1024){
                            int h = c>>6, d = c&63;
                            g_k[(((size_t)(bb*NH+h))*SQL + sIdx)*HD + d] = v;
                        } else {
                            int cc = c-1024; int h = cc>>6, d = cc&63;
                            g_v[(((size_t)(bb*NH+h))*SQL + sIdx)*HD + d] = v;
                        }
                    }
                }
            }
        }
    }
}

// ---------------------------------------------------------------------------
// Tensor-core flash attention (tf32, unchanged from round 3).
// ---------------------------------------------------------------------------
#define KS_STRIDE 68
#define VS_STRIDE 72
#define PW_STRIDE 68
#define ATT_KS_U  (64*KS_STRIDE)
#define ATT_VS_U  (64*VS_STRIDE)
#define ATT_PW_U  (128*PW_STRIDE)
#define ATT_SMEM  ((ATT_KS_U + ATT_VS_U + ATT_PW_U)*4)

__global__ __launch_bounds__(256) void attn_tc(const int* __restrict__ lens)
{
    extern __shared__ unsigned sm[];
    unsigned* Ks = sm;
    unsigned* Vs = sm + ATT_KS_U;
    unsigned* Pw = sm + ATT_KS_U + ATT_VS_U;

    int bh = blockIdx.x;
    int qb = blockIdx.y;
    int b  = bh >> 4;
    int h  = bh & 15;
    int tid  = threadIdx.x;
    int lane = tid & 31;
    int w    = tid >> 5;
    int q0   = qb*128;

    const float* qbase = g_q + (size_t)bh*SQL*HD;
    const float* kbase = g_k + (size_t)bh*SQL*HD;
    const float* vbase = g_v + (size_t)bh*SQL*HD;

    #pragma unroll
    for (int i=0;i<8;i++){
        int id = tid + i*256;
        int row = id>>4, d4 = (id&15)*4;
        float4 t = *reinterpret_cast<const float4*>(qbase + (size_t)(q0+row)*HD + d4);
        uint4 u = { f2tf(t.x), f2tf(t.y), f2tf(t.z), f2tf(t.w) };
        *reinterpret_cast<uint4*>(&Pw[row*PW_STRIDE + d4]) = u;
    }
    __syncthreads();

    unsigned aQ[8][4];
    {
        int m0 = w*16 + (lane>>2);
        #pragma unroll
        for (int ks=0; ks<8; ks++){
            int k = ks*8 + (lane&3);
            aQ[ks][0] = Pw[ m0   *PW_STRIDE + k];
            aQ[ks][1] = Pw[(m0+8)*PW_STRIDE + k];
            aQ[ks][2] = Pw[ m0   *PW_STRIDE + k+4];
            aQ[ks][3] = Pw[(m0+8)*PW_STRIDE + k+4];
        }
    }
    __syncthreads();

    int qrow0 = q0 + w*16 + (lane>>2);
    int qrow1 = qrow0 + 8;
    int lr0   = w*16 + (lane>>2);

    float Oacc[8][4];
    #pragma unroll
    for (int i=0;i<8;i++)
        #pragma unroll
        for (int e=0;e<4;e++) Oacc[i][e]=0.f;
    float mi0=-1e30f, mi1=-1e30f, li0=0.f, li1=0.f;

    int len  = lens[b];
    int kmax = min(q0+127, len-1);
    int nkb  = (kmax>>6) + 1;

    for (int kb=0; kb<nkb; kb++){
        int k0 = kb*64;
        __syncthreads();
        #pragma unroll
        for (int i=0;i<4;i++){
            int id = tid + i*256;
            int kr = id>>4, d4 = (id&15)*4;
            float4 tk = *reinterpret_cast<const float4*>(kbase + (size_t)(k0+kr)*HD + d4);
            float4 tv = *reinterpret_cast<const float4*>(vbase + (size_t)(k0+kr)*HD + d4);
            uint4 uk = { f2tf(tk.x), f2tf(tk.y), f2tf(tk.z), f2tf(tk.w) };
            uint4 uv = { f2tf(tv.x), f2tf(tv.y), f2tf(tv.z), f2tf(tv.w) };
            *reinterpret_cast<uint4*>(&Ks[kr*KS_STRIDE + d4]) = uk;
            *reinterpret_cast<uint4*>(&Vs[kr*VS_STRIDE + d4]) = uv;
        }
        __syncthreads();

        float sc[8][4];
        #pragma unroll
        for (int nf=0; nf<8; nf++){
            sc[nf][0]=0.f; sc[nf][1]=0.f; sc[nf][2]=0.f; sc[nf][3]=0.f;
            int n0 = nf*8 + (lane>>2);
            #pragma unroll
            for (int ks=0; ks<8; ks++){
                unsigned bfr[2];
                bfr[0] = Ks[n0*KS_STRIDE + ks*8 +     (lane&3)];
                bfr[1] = Ks[n0*KS_STRIDE + ks*8 + 4 + (lane&3)];
                mma_tf32(sc[nf], aQ[ks], bfr);
            }
        }

        #pragma unroll
        for (int nf=0; nf<8; nf++){
            int jc = k0 + nf*8 + 2*(lane&3);
            #pragma unroll
            for (int e=0; e<4; e++){
                int j   = jc + (e&1);
                int row = (e>=2) ? qrow1 : qrow0;
                float v = sc[nf][e]*0.125f;
                sc[nf][e] = (j<=row && j<len) ? v : -1e30f;
            }
        }

        float rmax0=-1e30f, rmax1=-1e30f;
        #pragma unroll
        for (int nf=0; nf<8; nf++){
            rmax0 = fmaxf(rmax0, fmaxf(sc[nf][0], sc[nf][1]));
            rmax1 = fmaxf(rmax1, fmaxf(sc[nf][2], sc[nf][3]));
        }
        rmax0 = fmaxf(rmax0, __shfl_xor_sync(0xffffffffu, rmax0, 1));
        rmax0 = fmaxf(rmax0, __shfl_xor_sync(0xffffffffu, rmax0, 2));
        rmax1 = fmaxf(rmax1, __shfl_xor_sync(0xffffffffu, rmax1, 1));
        rmax1 = fmaxf(rmax1, __shfl_xor_sync(0xffffffffu, rmax1, 2));

        float mn0 = fmaxf(mi0, rmax0);
        float mn1 = fmaxf(mi1, rmax1);
        float corr0 = __expf(mi0 - mn0);
        float corr1 = __expf(mi1 - mn1);
        mi0 = mn0; mi1 = mn1;

        float rs0=0.f, rs1=0.f;
        #pragma unroll
        for (int nf=0; nf<8; nf++){
            sc[nf][0] = __expf(sc[nf][0]-mn0);
            sc[nf][1] = __expf(sc[nf][1]-mn0);
            sc[nf][2] = __expf(sc[nf][2]-mn1);
            sc[nf][3] = __expf(sc[nf][3]-mn1);
            rs0 += sc[nf][0]+sc[nf][1];
            rs1 += sc[nf][2]+sc[nf][3];
        }
        rs0 += __shfl_xor_sync(0xffffffffu, rs0, 1);
        rs0 += __shfl_xor_sync(0xffffffffu, rs0, 2);
        rs1 += __shfl_xor_sync(0xffffffffu, rs1, 1);
        rs1 += __shfl_xor_sync(0xffffffffu, rs1, 2);
        li0 = li0*corr0 + rs0;
        li1 = li1*corr1 + rs1;

        #pragma unroll
        for (int nf=0; nf<8; nf++){
            Oacc[nf][0]*=corr0; Oacc[nf][1]*=corr0;
            Oacc[nf][2]*=corr1; Oacc[nf][3]*=corr1;
        }

        #pragma unroll
        for (int nf=0; nf<8; nf++){
            int c = nf*8 + 2*(lane&3);
            uint2 p01 = { f2tf(sc[nf][0]), f2tf(sc[nf][1]) };
            uint2 p23 = { f2tf(sc[nf][2]), f2tf(sc[nf][3]) };
            *reinterpret_cast<uint2*>(&Pw[ lr0   *PW_STRIDE + c]) = p01;
            *reinterpret_cast<uint2*>(&Pw[(lr0+8)*PW_STRIDE + c]) = p23;
        }
        __syncwarp();

        #pragma unroll
        for (int ks=0; ks<8; ks++){
            unsigned aP[4];
            aP[0] = Pw[ lr0   *PW_STRIDE + ks*8 +     (lane&3)];
            aP[1] = Pw[(lr0+8)*PW_STRIDE + ks*8 +     (lane&3)];
            aP[2] = Pw[ lr0   *PW_STRIDE + ks*8 + 4 + (lane&3)];
            aP[3] = Pw[(lr0+8)*PW_STRIDE + ks*8 + 4 + (lane&3)];
            #pragma unroll
            for (int df=0; df<8; df++){
                unsigned bfr[2];
                bfr[0] = Vs[(ks*8 +     (lane&3))*VS_STRIDE + df*8 + (lane>>2)];
                bfr[1] = Vs[(ks*8 + 4 + (lane&3))*VS_STRIDE + df*8 + (lane>>2)];
                mma_tf32(Oacc[df], aP, bfr);
            }
        }
    }

    float inv0 = 1.f/li0, inv1 = 1.f/li1;
    float* o0 = g_ao + ((size_t)(b*SQL + qrow0))*DM + h*HD;
    float* o1 = g_ao + ((size_t)(b*SQL + qrow1))*DM + h*HD;
    #pragma unroll
    for (int df=0; df<8; df++){
        int c = df*8 + 2*(lane&3);
        float2 v0 = { Oacc[df][0]*inv0, Oacc[df][1]*inv0 };
        float2 v1 = { Oacc[df][2]*inv1, Oacc[df][3]*inv1 };
        *reinterpret_cast<float2*>(o0 + c) = v0;
        *reinterpret_cast<float2*>(o1 + c) = v1;
    }
}

// ---------------------------------------------------------------------------
extern "C" void kernel_launch(void* const* d_in, const int* in_sizes, int n_in,
                              void* d_out, int out_size)
{
    const float* x     = (const float*)d_in[0];
    const int*   lens  = (const int*)  d_in[2];
    const float* Wq    = (const float*)d_in[3];
    const float* bq    = (const float*)d_in[4];
    const float* Wkv   = (const float*)d_in[5];
    const float* bkv   = (const float*)d_in[6];
    const float* Wo    = (const float*)d_in[7];
    const float* bo    = (const float*)d_in[8];
    const float* gamma = (const float*)d_in[9];
    const float* beta  = (const float*)d_in[10];
    float* out = (float*)d_out;

    cudaFuncSetAttribute(gemm_bf<0>, cudaFuncAttributeMaxDynamicSharedMemorySize, GEMM_SMEM);
    cudaFuncSetAttribute(gemm_bf<1>, cudaFuncAttributeMaxDynamicSharedMemorySize, GEMM_SMEM);
    cudaFuncSetAttribute(gemm_bf<2>, cudaFuncAttributeMaxDynamicSharedMemorySize, GEMM_SMEM);
    cudaFuncSetAttribute(attn_tc,    cudaFuncAttributeMaxDynamicSharedMemorySize, ATT_SMEM);

    ln_kernel <<<NTOK, 256>>>(x, gamma, beta);
    gemm_bf<0><<<dim3(8, 64), 256, GEMM_SMEM>>>(Wq,  1024, bq,  nullptr);
    gemm_bf<1><<<dim3(16,64), 256, GEMM_SMEM>>>(Wkv, 2048, bkv, nullptr);
    attn_tc   <<<dim3(128,8), 256, ATT_SMEM>>>(lens);
    gemm_bf<2><<<dim3(8, 64), 256, GEMM_SMEM>>>(Wo,  1024, bo,  out);
}

// round 5
// speedup vs baseline: 5.4802x; 1.1793x over previous
#include <cuda_runtime.h>
#include <cuda_bf16.h>
#include <math.h>

#define NB 8
#define SQL 1024
#define DM 1024
#define NH 16
#define HD 64
#define NTOK (NB*SQL)

// Scratch (no allocations allowed) — __device__ globals.
__device__ float    g_ln[NTOK*DM];          // LayerNorm(x), also the residual
__device__ unsigned g_qu[NB*NH*SQL*32];     // Q bf16x2, [b,h,s,d/2], pre-scaled by 0.125
__device__ unsigned g_ku[NB*NH*SQL*32];     // K bf16x2
__device__ unsigned g_vu[NB*NH*SQL*32];     // V bf16x2
__device__ float    g_ao[NTOK*DM];          // attention output, [b,s,h*d]

__device__ __forceinline__ unsigned packbf(float lo, float hi){
    __nv_bfloat162 h = __floats2bfloat162_rn(lo, hi);
    return *reinterpret_cast<unsigned*>(&h);
}
__device__ __forceinline__ unsigned s2u(const void* p){
    return (unsigned)__cvta_generic_to_shared(p);
}
__device__ __forceinline__ void mma_bf16(float* c, const unsigned* a, const unsigned* b){
    asm volatile(
        "mma.sync.aligned.m16n8k16.row.col.f32.bf16.bf16.f32 "
        "{%0,%1,%2,%3}, {%4,%5,%6,%7}, {%8,%9}, {%0,%1,%2,%3};\n"
        : "+f"(c[0]), "+f"(c[1]), "+f"(c[2]), "+f"(c[3])
        : "r"(a[0]), "r"(a[1]), "r"(a[2]), "r"(a[3]), "r"(b[0]), "r"(b[1]));
}
__device__ __forceinline__ void ldsm4(unsigned* r, unsigned addr){
    asm volatile("ldmatrix.sync.aligned.m8n8.x4.shared.b16 {%0,%1,%2,%3}, [%4];"
        : "=r"(r[0]), "=r"(r[1]), "=r"(r[2]), "=r"(r[3]) : "r"(addr));
}
__device__ __forceinline__ void ldsm4t(unsigned* r, unsigned addr){
    asm volatile("ldmatrix.sync.aligned.m8n8.x4.trans.shared.b16 {%0,%1,%2,%3}, [%4];"
        : "=r"(r[0]), "=r"(r[1]), "=r"(r[2]), "=r"(r[3]) : "r"(addr));
}

// ---------------------------------------------------------------------------
// LayerNorm: one block per token row (1024 elems), 256 threads, float4 IO.
// ---------------------------------------------------------------------------
__global__ __launch_bounds__(256) void ln_kernel(const float* __restrict__ x,
                                                 const float* __restrict__ gamma,
                                                 const float* __restrict__ beta)
{
    int row = blockIdx.x;
    int tid = threadIdx.x;
    float4 v = reinterpret_cast<const float4*>(x + (size_t)row*DM)[tid];
    float s  = v.x+v.y+v.z+v.w;
    float ss = v.x*v.x+v.y*v.y+v.z*v.z+v.w*v.w;
    #pragma unroll
    for (int o=16;o;o>>=1){
        s  += __shfl_xor_sync(0xffffffffu, s,  o);
        ss += __shfl_xor_sync(0xffffffffu, ss, o);
    }
    __shared__ float ws[8], wss[8];
    int wid = tid>>5, lid = tid&31;
    if (lid==0){ ws[wid]=s; wss[wid]=ss; }
    __syncthreads();
    if (tid==0){
        float a=0.f,c=0.f;
        #pragma unroll
        for (int i=0;i<8;i++){ a+=ws[i]; c+=wss[i]; }
        ws[0]=a; wss[0]=c;
    }
    __syncthreads();
    float mean = ws[0]*(1.0f/DM);
    float var  = wss[0]*(1.0f/DM) - mean*mean;
    float rstd = rsqrtf(var + 1e-3f);
    float4 g  = reinterpret_cast<const float4*>(gamma)[tid];
    float4 bt = reinterpret_cast<const float4*>(beta)[tid];
    float4 o;
    o.x = (v.x-mean)*rstd*g.x + bt.x;
    o.y = (v.y-mean)*rstd*g.y + bt.y;
    o.z = (v.z-mean)*rstd*g.z + bt.z;
    o.w = (v.w-mean)*rstd*g.w + bt.w;
    reinterpret_cast<float4*>(g_ln + (size_t)row*DM)[tid] = o;
}

// ---------------------------------------------------------------------------
// bf16 tensor-core GEMM: C[8192, N] = A[8192,1024] @ W[1024, N]
// 128x128x32 tiles, 256 threads / 8 warps (2x4), warp tile 64x32,
// mma.m16n8k16.bf16, double-buffered smem, fp32 gmem -> inline bf16 cvt.
// MODE 0: merged QKV (grid.x=24): cols 0..1023 -> Q (scaled 0.125, bf16),
//         1024..2047 -> K (bf16), 2048..3071 -> V (bf16).
// MODE 2: A=g_ao, out = acc + bias + residual (fp32).
// ---------------------------------------------------------------------------
#define BKT   32
#define ASTR  20
#define BSTR  136
#define ATILE_U (128*ASTR)
#define BTILE_U (16*BSTR)
#define GEMM_SMEM ((2*ATILE_U + 2*BTILE_U)*4)   // 37888 bytes

template<int MODE>
__global__ __launch_bounds__(256) void gemm_bf(const float* __restrict__ W1,
                                               const float* __restrict__ W2,
                                               const float* __restrict__ b1,
                                               const float* __restrict__ b2,
                                               float* __restrict__ Cout)
{
    extern __shared__ unsigned smu[];
    const float* Aptr = (MODE==2) ? g_ao : g_ln;

    int tid  = threadIdx.x;
    int lane = tid & 31;
    int warp = tid >> 5;
    int wm = warp >> 2, wn = warp & 3;
    int row0 = blockIdx.y * 128;
    int col0 = blockIdx.x * 128;

    const float* W; int ldw, wc0;
    if (MODE == 0){
        if (col0 < 1024){ W=W1; ldw=1024; wc0=col0; }
        else            { W=W2; ldw=2048; wc0=col0-1024; }
    } else { W=W1; ldw=1024; wc0=col0; }

    float acc[4][4][4];
    #pragma unroll
    for (int i=0;i<4;i++)
        #pragma unroll
        for (int j=0;j<4;j++)
            #pragma unroll
            for (int e=0;e<4;e++) acc[i][j][e]=0.f;

    float4 aR[4], bRa[2], bRb[2];

    {
        #pragma unroll
        for (int i=0;i<4;i++){
            int id = tid + i*256;
            aR[i] = *reinterpret_cast<const float4*>(
                        Aptr + (size_t)(row0 + (id>>3))*DM + (id&7)*4);
        }
        #pragma unroll
        for (int i=0;i<2;i++){
            int k2 = (tid>>5) + i*8;
            int n4 = (tid&31)*4;
            bRa[i] = *reinterpret_cast<const float4*>(W + (size_t)(2*k2  )*ldw + wc0 + n4);
            bRb[i] = *reinterpret_cast<const float4*>(W + (size_t)(2*k2+1)*ldw + wc0 + n4);
        }
        unsigned* Ad = smu;
        unsigned* Bd = smu + 2*ATILE_U;
        #pragma unroll
        for (int i=0;i<4;i++){
            int id = tid + i*256;
            int m = id>>3, k2 = (id&7)*2;
            uint2 u = { packbf(aR[i].x, aR[i].y), packbf(aR[i].z, aR[i].w) };
            *reinterpret_cast<uint2*>(&Ad[m*ASTR + k2]) = u;
        }
        #pragma unroll
        for (int i=0;i<2;i++){
            int k2 = (tid>>5) + i*8;
            int n4 = (tid&31)*4;
            uint4 u = { packbf(bRa[i].x, bRb[i].x), packbf(bRa[i].y, bRb[i].y),
                        packbf(bRa[i].z, bRb[i].z), packbf(bRa[i].w, bRb[i].w) };
            *reinterpret_cast<uint4*>(&Bd[k2*BSTR + n4]) = u;
        }
    }
    __syncthreads();

    int buf = 0;
    const int NKT = DM / BKT;
    for (int kt = 0; kt < NKT; kt++){
        if (kt+1 < NKT){
            int k0 = (kt+1)*BKT;
            #pragma unroll
            for (int i=0;i<4;i++){
                int id = tid + i*256;
                aR[i] = *reinterpret_cast<const float4*>(
                            Aptr + (size_t)(row0 + (id>>3))*DM + k0 + (id&7)*4);
            }
            #pragma unroll
            for (int i=0;i<2;i++){
                int k2 = (tid>>5) + i*8;
                int n4 = (tid&31)*4;
                bRa[i] = *reinterpret_cast<const float4*>(W + (size_t)(k0+2*k2  )*ldw + wc0 + n4);
                bRb[i] = *reinterpret_cast<const float4*>(W + (size_t)(k0+2*k2+1)*ldw + wc0 + n4);
            }
        }

        const unsigned* Ac = smu + buf*ATILE_U;
        const unsigned* Bc = smu + 2*ATILE_U + buf*BTILE_U;
        #pragma unroll
        for (int ks=0; ks<2; ks++){
            int kb = ks*8;
            unsigned afr[4][4], bfr[4][2];
            #pragma unroll
            for (int mf=0; mf<4; mf++){
                int m0 = wm*64 + mf*16 + (lane>>2);
                afr[mf][0] = Ac[ m0   *ASTR + kb +     (lane&3)];
                afr[mf][1] = Ac[(m0+8)*ASTR + kb +     (lane&3)];
                afr[mf][2] = Ac[ m0   *ASTR + kb + 4 + (lane&3)];
                afr[mf][3] = Ac[(m0+8)*ASTR + kb + 4 + (lane&3)];
            }
            #pragma unroll
            for (int nf=0; nf<4; nf++){
                int n0 = wn*32 + nf*8 + (lane>>2);
                bfr[nf][0] = Bc[(kb +     (lane&3))*BSTR + n0];
                bfr[nf][1] = Bc[(kb + 4 + (lane&3))*BSTR + n0];
            }
            #pragma unroll
            for (int mf=0; mf<4; mf++)
                #pragma unroll
                for (int nf=0; nf<4; nf++)
                    mma_bf16(acc[mf][nf], afr[mf], bfr[nf]);
        }

        if (kt+1 < NKT){
            unsigned* Ad = smu + (buf^1)*ATILE_U;
            unsigned* Bd = smu + 2*ATILE_U + (buf^1)*BTILE_U;
            #pragma unroll
            for (int i=0;i<4;i++){
                int id = tid + i*256;
                int m = id>>3, k2 = (id&7)*2;
                uint2 u = { packbf(aR[i].x, aR[i].y), packbf(aR[i].z, aR[i].w) };
                *reinterpret_cast<uint2*>(&Ad[m*ASTR + k2]) = u;
            }
            #pragma unroll
            for (int i=0;i<2;i++){
                int k2 = (tid>>5) + i*8;
                int n4 = (tid&31)*4;
                uint4 u = { packbf(bRa[i].x, bRb[i].x), packbf(bRa[i].y, bRb[i].y),
                            packbf(bRa[i].z, bRb[i].z), packbf(bRa[i].w, bRb[i].w) };
                *reinterpret_cast<uint4*>(&Bd[k2*BSTR + n4]) = u;
            }
            __syncthreads();
            buf ^= 1;
        }
    }

    // ---- epilogue
    if (MODE == 2){
        #pragma unroll
        for (int mf=0; mf<4; mf++)
            #pragma unroll
            for (int nf=0; nf<4; nf++)
                #pragma unroll
                for (int e=0; e<4; e++){
                    int r = row0 + wm*64 + mf*16 + (lane>>2) + ((e>=2)?8:0);
                    int c = col0 + wn*32 + nf*8 + 2*(lane&3) + (e&1);
                    Cout[(size_t)r*DM + c] = acc[mf][nf][e] + b1[c] + g_ln[(size_t)r*DM + c];
                }
    } else {
        #pragma unroll
        for (int mf=0; mf<4; mf++){
            #pragma unroll
            for (int nf=0; nf<4; nf++){
                int c = col0 + wn*32 + nf*8 + 2*(lane&3);
                #pragma unroll
                for (int half=0; half<2; half++){
                    int r = row0 + wm*64 + mf*16 + (lane>>2) + half*8;
                    int bb = r >> 10, sIdx = r & 1023;
                    float v0 = acc[mf][nf][half*2+0];
                    float v1 = acc[mf][nf][half*2+1];
                    if (c < 1024){
                        unsigned u = packbf((v0 + b1[c])*0.125f, (v1 + b1[c+1])*0.125f);
                        int h = c>>6, d = c&63;
                        g_qu[(((size_t)(bb*NH+h))*SQL + sIdx)*32 + (d>>1)] = u;
                    } else if (c < 2048){
                        int cc = c-1024;
                        unsigned u = packbf(v0 + b2[cc], v1 + b2[cc+1]);
                        int h = cc>>6, d = cc&63;
                        g_ku[(((size_t)(bb*NH+h))*SQL + sIdx)*32 + (d>>1)] = u;
                    } else {
                        int cc = c-2048;
                        unsigned u = packbf(v0 + b2[cc+1024], v1 + b2[cc+1025]);
                        int h = cc>>6, d = cc&63;
                        g_vu[(((size_t)(bb*NH+h))*SQL + sIdx)*32 + (d>>1)] = u;
                    }
                }
            }
        }
    }
}

// ---------------------------------------------------------------------------
// bf16 tensor-core flash attention.
// Block = (bh, 128-query tile), 256 threads / 8 warps; warp owns 16 q rows.
// K/V in bf16 gmem, 64-key tiles in smem (stride 36 uints = conflict-free),
// fragments via ldmatrix.x4 (trans for V), mma.m16n8k16.bf16.
// Q is pre-scaled by 1/8 at the QKV-GEMM epilogue.
// ---------------------------------------------------------------------------
#define ATSTR 36
#define ATT_KS_U (64*ATSTR)
#define ATT_VS_U (64*ATSTR)
#define ATT_PW_U (128*ATSTR)
#define ATT_SMEM ((ATT_KS_U + ATT_VS_U + ATT_PW_U)*4)   // 36864 bytes

__global__ __launch_bounds__(256) void attn_bf(const int* __restrict__ lens)
{
    extern __shared__ unsigned sm[];
    unsigned* Ks = sm;
    unsigned* Vs = sm + ATT_KS_U;
    unsigned* Pw = sm + ATT_KS_U + ATT_VS_U;   // Q staging, then warp-private P

    int bh = blockIdx.x;
    int qb = blockIdx.y;
    int b  = bh >> 4;
    int h  = bh & 15;
    int tid  = threadIdx.x;
    int lane = tid & 31;
    int w    = tid >> 5;
    int q0   = qb*128;
    int sub  = lane >> 3;      // ldmatrix sub-matrix index
    int rr   = lane & 7;       // ldmatrix row-within-matrix

    const uint4* qg = reinterpret_cast<const uint4*>(g_qu + ((size_t)bh*SQL + q0)*32);
    const uint4* kg = reinterpret_cast<const uint4*>(g_ku + (size_t)bh*SQL*32);
    const uint4* vg = reinterpret_cast<const uint4*>(g_vu + (size_t)bh*SQL*32);

    // ---- stage Q tile (bf16, already scaled) into Pw
    #pragma unroll
    for (int i=0;i<4;i++){
        int id = tid + i*256;
        int row = id>>3, u4 = id&7;
        *reinterpret_cast<uint4*>(&Pw[row*ATSTR + u4*4]) = qg[row*8 + u4];
    }
    __syncthreads();

    // ---- Q A-fragments (4 ksteps x 4 regs)
    unsigned aQ[4][4];
    {
        unsigned abase = s2u(Pw) + (unsigned)(((w*16 + (sub&1)*8 + rr)*ATSTR + (sub>>1)*4)*4);
        #pragma unroll
        for (int ks=0; ks<4; ks++) ldsm4(aQ[ks], abase + ks*8*4);
    }
    // (Pw reuse below is warp-private: warp w only touches rows w*16..w*16+15)

    int qrow0 = q0 + w*16 + (lane>>2);
    int qrow1 = qrow0 + 8;
    int lr0   = w*16 + (lane>>2);

    float Oacc[8][4];
    #pragma unroll
    for (int i=0;i<8;i++)
        #pragma unroll
        for (int e=0;e<4;e++) Oacc[i][e]=0.f;
    float mi0=-1e30f, mi1=-1e30f, li0=0.f, li1=0.f;

    int len  = lens[b];
    int kmax = min(q0+127, len-1);
    int nkb  = (kmax>>6) + 1;

    unsigned ks_u = s2u(Ks);
    unsigned vs_u = s2u(Vs);
    unsigned pw_u = s2u(Pw);

    for (int kb=0; kb<nkb; kb++){
        int k0 = kb*64;
        __syncthreads();
        // load K,V 64x64 bf16 tiles (8KB each)
        #pragma unroll
        for (int i=0;i<2;i++){
            int id = tid + i*256;
            int kr = id>>3, u4 = id&7;
            *reinterpret_cast<uint4*>(&Ks[kr*ATSTR + u4*4]) = kg[(size_t)(k0+kr)*8 + u4];
            *reinterpret_cast<uint4*>(&Vs[kr*ATSTR + u4*4]) = vg[(size_t)(k0+kr)*8 + u4];
        }
        __syncthreads();

        // ---- S = Q K^T (Q pre-scaled)
        float sc[8][4];
        #pragma unroll
        for (int nf=0; nf<8; nf++){
            sc[nf][0]=0.f; sc[nf][1]=0.f; sc[nf][2]=0.f; sc[nf][3]=0.f;
            unsigned kbase_a = ks_u + (unsigned)(((nf*8 + rr)*ATSTR + sub*4)*4);
            #pragma unroll
            for (int ksp=0; ksp<2; ksp++){
                unsigned bb4[4];
                ldsm4(bb4, kbase_a + ksp*16*4);
                mma_bf16(sc[nf], aQ[2*ksp  ], bb4);
                mma_bf16(sc[nf], aQ[2*ksp+1], bb4+2);
            }
        }

        // ---- mask
        #pragma unroll
        for (int nf=0; nf<8; nf++){
            int jc = k0 + nf*8 + 2*(lane&3);
            #pragma unroll
            for (int e=0; e<4; e++){
                int j   = jc + (e&1);
                int row = (e>=2) ? qrow1 : qrow0;
                sc[nf][e] = (j<=row && j<len) ? sc[nf][e] : -1e30f;
            }
        }

        // ---- online softmax
        float rmax0=-1e30f, rmax1=-1e30f;
        #pragma unroll
        for (int nf=0; nf<8; nf++){
            rmax0 = fmaxf(rmax0, fmaxf(sc[nf][0], sc[nf][1]));
            rmax1 = fmaxf(rmax1, fmaxf(sc[nf][2], sc[nf][3]));
        }
        rmax0 = fmaxf(rmax0, __shfl_xor_sync(0xffffffffu, rmax0, 1));
        rmax0 = fmaxf(rmax0, __shfl_xor_sync(0xffffffffu, rmax0, 2));
        rmax1 = fmaxf(rmax1, __shfl_xor_sync(0xffffffffu, rmax1, 1));
        rmax1 = fmaxf(rmax1, __shfl_xor_sync(0xffffffffu, rmax1, 2));

        float mn0 = fmaxf(mi0, rmax0);
        float mn1 = fmaxf(mi1, rmax1);
        float corr0 = __expf(mi0 - mn0);
        float corr1 = __expf(mi1 - mn1);
        mi0 = mn0; mi1 = mn1;

        float rs0=0.f, rs1=0.f;
        #pragma unroll
        for (int nf=0; nf<8; nf++){
            sc[nf][0] = __expf(sc[nf][0]-mn0);
            sc[nf][1] = __expf(sc[nf][1]-mn0);
            sc[nf][2] = __expf(sc[nf][2]-mn1);
            sc[nf][3] = __expf(sc[nf][3]-mn1);
            rs0 += sc[nf][0]+sc[nf][1];
            rs1 += sc[nf][2]+sc[nf][3];
        }
        rs0 += __shfl_xor_sync(0xffffffffu, rs0, 1);
        rs0 += __shfl_xor_sync(0xffffffffu, rs0, 2);
        rs1 += __shfl_xor_sync(0xffffffffu, rs1, 1);
        rs1 += __shfl_xor_sync(0xffffffffu, rs1, 2);
        li0 = li0*corr0 + rs0;
        li1 = li1*corr1 + rs1;

        #pragma unroll
        for (int nf=0; nf<8; nf++){
            Oacc[nf][0]*=corr0; Oacc[nf][1]*=corr0;
            Oacc[nf][2]*=corr1; Oacc[nf][3]*=corr1;
        }

        // ---- P -> warp-private Pw rows (bf16x2)
        #pragma unroll
        for (int nf=0; nf<8; nf++){
            Pw[ lr0   *ATSTR + nf*4 + (lane&3)] = packbf(sc[nf][0], sc[nf][1]);
            Pw[(lr0+8)*ATSTR + nf*4 + (lane&3)] = packbf(sc[nf][2], sc[nf][3]);
        }
        __syncwarp();

        // ---- O += P V
        #pragma unroll
        for (int ks=0; ks<4; ks++){
            unsigned aP[4];
            ldsm4(aP, pw_u + (unsigned)(((w*16 + (sub&1)*8 + rr)*ATSTR + ks*8 + (sub>>1)*4)*4));
            unsigned vrow = vs_u + (unsigned)(((ks*16 + (sub&1)*8 + rr)*ATSTR + (sub>>1)*4)*4);
            #pragma unroll
            for (int dfp=0; dfp<4; dfp++){
                unsigned bb4[4];
                ldsm4t(bb4, vrow + dfp*8*4);
                mma_bf16(Oacc[2*dfp  ], aP, bb4);
                mma_bf16(Oacc[2*dfp+1], aP, bb4+2);
            }
        }
    }

    // ---- write O
    float inv0 = 1.f/li0, inv1 = 1.f/li1;
    float* o0 = g_ao + ((size_t)(b*SQL + qrow0))*DM + h*HD;
    float* o1 = g_ao + ((size_t)(b*SQL + qrow1))*DM + h*HD;
    #pragma unroll
    for (int df=0; df<8; df++){
        int c = df*8 + 2*(lane&3);
        float2 v0 = { Oacc[df][0]*inv0, Oacc[df][1]*inv0 };
        float2 v1 = { Oacc[df][2]*inv1, Oacc[df][3]*inv1 };
        *reinterpret_cast<float2*>(o0 + c) = v0;
        *reinterpret_cast<float2*>(o1 + c) = v1;
    }
}

// ---------------------------------------------------------------------------
extern "C" void kernel_launch(void* const* d_in, const int* in_sizes, int n_in,
                              void* d_out, int out_size)
{
    const float* x     = (const float*)d_in[0];
    const int*   lens  = (const int*)  d_in[2];
    const float* Wq    = (const float*)d_in[3];
    const float* bq    = (const float*)d_in[4];
    const float* Wkv   = (const float*)d_in[5];
    const float* bkv   = (const float*)d_in[6];
    const float* Wo    = (const float*)d_in[7];
    const float* bo    = (const float*)d_in[8];
    const float* gamma = (const float*)d_in[9];
    const float* beta  = (const float*)d_in[10];
    float* out = (float*)d_out;

    cudaFuncSetAttribute(gemm_bf<0>, cudaFuncAttributeMaxDynamicSharedMemorySize, GEMM_SMEM);
    cudaFuncSetAttribute(gemm_bf<2>, cudaFuncAttributeMaxDynamicSharedMemorySize, GEMM_SMEM);
    cudaFuncSetAttribute(attn_bf,    cudaFuncAttributeMaxDynamicSharedMemorySize, ATT_SMEM);

    ln_kernel <<<NTOK, 256>>>(x, gamma, beta);
    gemm_bf<0><<<dim3(24,64), 256, GEMM_SMEM>>>(Wq, Wkv, bq, bkv, nullptr);
    attn_bf   <<<dim3(128,8), 256, ATT_SMEM>>>(lens);
    gemm_bf<2><<<dim3(8, 64), 256, GEMM_SMEM>>>(Wo, nullptr, bo, nullptr, out);
}

// round 6
// speedup vs baseline: 6.9809x; 1.2738x over previous
#include <cuda_runtime.h>
#include <cuda_bf16.h>
#include <math.h>

#define NB 8
#define SQL 1024
#define DM 1024
#define NH 16
#define HD 64
#define NTOK (NB*SQL)

// Scratch (no allocations allowed) — __device__ globals.
__device__ float    g_ln [NTOK*DM];         // LayerNorm(x) fp32, residual
__device__ unsigned g_lnb[NTOK*512];        // LayerNorm(x) bf16x2 (GEMM A)
__device__ unsigned g_qu [NB*NH*SQL*32];    // Q bf16x2, [b,h,s,d/2], pre-scaled 0.125
__device__ unsigned g_ku [NB*NH*SQL*32];    // K bf16x2
__device__ unsigned g_vu [NB*NH*SQL*32];    // V bf16x2
__device__ unsigned g_aob[NTOK*512];        // attention out bf16x2 (GEMM A)
__device__ unsigned g_wqkv[1024*1536];      // [Wq|Wkv] bf16x2, [k][n/2], n=3072
__device__ unsigned g_wob [1024*512];       // Wo bf16x2, [k][n/2], n=1024

__device__ __forceinline__ unsigned packbf(float lo, float hi){
    __nv_bfloat162 h = __floats2bfloat162_rn(lo, hi);
    return *reinterpret_cast<unsigned*>(&h);
}
__device__ __forceinline__ unsigned s2u(const void* p){
    return (unsigned)__cvta_generic_to_shared(p);
}
__device__ __forceinline__ void mma_bf16(float* c, const unsigned* a, const unsigned* b){
    asm volatile(
        "mma.sync.aligned.m16n8k16.row.col.f32.bf16.bf16.f32 "
        "{%0,%1,%2,%3}, {%4,%5,%6,%7}, {%8,%9}, {%0,%1,%2,%3};\n"
        : "+f"(c[0]), "+f"(c[1]), "+f"(c[2]), "+f"(c[3])
        : "r"(a[0]), "r"(a[1]), "r"(a[2]), "r"(a[3]), "r"(b[0]), "r"(b[1]));
}
__device__ __forceinline__ void ldsm4(unsigned* r, unsigned addr){
    asm volatile("ldmatrix.sync.aligned.m8n8.x4.shared.b16 {%0,%1,%2,%3}, [%4];"
        : "=r"(r[0]), "=r"(r[1]), "=r"(r[2]), "=r"(r[3]) : "r"(addr));
}
__device__ __forceinline__ void ldsm4t(unsigned* r, unsigned addr){
    asm volatile("ldmatrix.sync.aligned.m8n8.x4.trans.shared.b16 {%0,%1,%2,%3}, [%4];"
        : "=r"(r[0]), "=r"(r[1]), "=r"(r[2]), "=r"(r[3]) : "r"(addr));
}
__device__ __forceinline__ void cpa16(unsigned saddr, const void* g){
    asm volatile("cp.async.cg.shared.global [%0], [%1], 16;" :: "r"(saddr), "l"(g) : "memory");
}
__device__ __forceinline__ void cpa_commit(){
    asm volatile("cp.async.commit_group;" ::: "memory");
}
template<int N> __device__ __forceinline__ void cpa_wait(){
    asm volatile("cp.async.wait_group %0;" :: "n"(N) : "memory");
}

// ---------------------------------------------------------------------------
// Weight conversion fp32 -> bf16x2 (one launch, ~4us).
// ---------------------------------------------------------------------------
__global__ __launch_bounds__(256) void wconv2(const float* __restrict__ Wq,
                                              const float* __restrict__ Wkv,
                                              const float* __restrict__ Wo)
{
    int id = blockIdx.x*256 + threadIdx.x;     // 0 .. 1048575, 4 elems each
    if (id < 786432){                          // qkv region: 1024 x 3072
        int e = id*4;
        int k = e / 3072, n = e % 3072;
        float4 v;
        if (n < 1024) v = *reinterpret_cast<const float4*>(Wq  + (size_t)k*1024 + n);
        else          v = *reinterpret_cast<const float4*>(Wkv + (size_t)k*2048 + (n-1024));
        uint2 u = { packbf(v.x, v.y), packbf(v.z, v.w) };
        *reinterpret_cast<uint2*>(&g_wqkv[(size_t)k*1536 + (n>>1)]) = u;
    } else {                                   // wo region: 1024 x 1024
        int e = (id - 786432)*4;
        float4 v = *reinterpret_cast<const float4*>(Wo + e);
        uint2 u = { packbf(v.x, v.y), packbf(v.z, v.w) };
        *reinterpret_cast<uint2*>(&g_wob[e>>1]) = u;
    }
}

// ---------------------------------------------------------------------------
// LayerNorm: one block per token row; writes fp32 residual + bf16 GEMM input.
// ---------------------------------------------------------------------------
__global__ __launch_bounds__(256) void ln_kernel(const float* __restrict__ x,
                                                 const float* __restrict__ gamma,
                                                 const float* __restrict__ beta)
{
    int row = blockIdx.x;
    int tid = threadIdx.x;
    float4 v = reinterpret_cast<const float4*>(x + (size_t)row*DM)[tid];
    float s  = v.x+v.y+v.z+v.w;
    float ss = v.x*v.x+v.y*v.y+v.z*v.z+v.w*v.w;
    #pragma unroll
    for (int o=16;o;o>>=1){
        s  += __shfl_xor_sync(0xffffffffu, s,  o);
        ss += __shfl_xor_sync(0xffffffffu, ss, o);
    }
    __shared__ float ws[8], wss[8];
    int wid = tid>>5, lid = tid&31;
    if (lid==0){ ws[wid]=s; wss[wid]=ss; }
    __syncthreads();
    if (tid==0){
        float a=0.f,c=0.f;
        #pragma unroll
        for (int i=0;i<8;i++){ a+=ws[i]; c+=wss[i]; }
        ws[0]=a; wss[0]=c;
    }
    __syncthreads();
    float mean = ws[0]*(1.0f/DM);
    float var  = wss[0]*(1.0f/DM) - mean*mean;
    float rstd = rsqrtf(var + 1e-3f);
    float4 g  = reinterpret_cast<const float4*>(gamma)[tid];
    float4 bt = reinterpret_cast<const float4*>(beta)[tid];
    float4 o;
    o.x = (v.x-mean)*rstd*g.x + bt.x;
    o.y = (v.y-mean)*rstd*g.y + bt.y;
    o.z = (v.z-mean)*rstd*g.z + bt.z;
    o.w = (v.w-mean)*rstd*g.w + bt.w;
    reinterpret_cast<float4*>(g_ln + (size_t)row*DM)[tid] = o;
    uint2 u = { packbf(o.x, o.y), packbf(o.z, o.w) };
    *reinterpret_cast<uint2*>(&g_lnb[(size_t)row*512 + tid*2]) = u;
}

// ---------------------------------------------------------------------------
// bf16 pipelined GEMM: C[8192,N] = A[8192,1024] @ W[1024,N], all bf16 in gmem.
// 128x128x32 tiles, 256 thr / 8 warps (2x4), warp tile 64x32, m16n8k16.
// cp.async 3-stage pipeline + ldmatrix fragments.
// Smem chunk layouts (16B units): A: m*5 + k/8 (pad-5); B: k*17 + n/8 (pad-17).
// MODE 0: A=g_lnb, B=g_wqkv(ldn 3072) -> scatter Q(*0.125)/K/V bf16.
// MODE 2: A=g_aob, B=g_wob(ldn 1024)  -> out = acc + bias + residual (fp32).
// ---------------------------------------------------------------------------
#define SSTAGE 18944                 // bytes per stage: A 10240 + B 8704
#define GEMM_SMEM (3*SSTAGE)         // 56832

template<int MODE>
__global__ __launch_bounds__(256) void gemm_cp(const float* __restrict__ b1,
                                               const float* __restrict__ b2,
                                               float* __restrict__ Cout)
{
    extern __shared__ unsigned char smem_raw[];
    unsigned smem_u = s2u(smem_raw);

    const uint4* Ag = reinterpret_cast<const uint4*>((MODE==2) ? g_aob : g_lnb);
    const uint4* Bg = reinterpret_cast<const uint4*>((MODE==2) ? g_wob : g_wqkv);
    const int ldn4  = (MODE==2) ? 128 : 384;    // uint4 per weight row

    int tid  = threadIdx.x;
    int lane = tid & 31;
    int warp = tid >> 5;
    int wm = warp >> 2, wn = warp & 3;
    int row0 = blockIdx.y * 128;
    int col0 = blockIdx.x * 128;
    int col4 = col0 >> 3;                        // col0 in uint4

    float acc[4][4][4];
    #pragma unroll
    for (int i=0;i<4;i++)
        #pragma unroll
        for (int j=0;j<4;j++)
            #pragma unroll
            for (int e=0;e<4;e++) acc[i][j][e]=0.f;

    const int NKT = 32;

    // ---- prologue: stages 0,1
    #pragma unroll
    for (int st=0; st<2; st++){
        unsigned ab = smem_u + st*SSTAGE;
        unsigned bb = ab + 10240;
        #pragma unroll
        for (int i=0;i<2;i++){
            int id = tid + i*256;
            int m = id>>2, c = id&3;
            cpa16(ab + (unsigned)((m*5 + c)*16),
                  Ag + (size_t)(row0+m)*128 + st*4 + c);
            int k = id>>4, c2 = id&15;
            cpa16(bb + (unsigned)((k*17 + c2)*16),
                  Bg + (size_t)(st*32+k)*ldn4 + col4 + c2);
        }
        cpa_commit();
    }

    int buf = 0;
    for (int kt = 0; kt < NKT; kt++){
        cpa_wait<1>();
        __syncthreads();

        unsigned abase = smem_u + buf*SSTAGE;
        unsigned bbase = abase + 10240;
        #pragma unroll
        for (int ks=0; ks<2; ks++){
            unsigned afr[4][4], bfr[2][4];
            #pragma unroll
            for (int mf=0; mf<4; mf++){
                int m0 = wm*64 + mf*16;
                ldsm4(afr[mf], abase +
                      (unsigned)((((m0 + (lane&15))*5) + ks*2 + (lane>>4))*16));
            }
            #pragma unroll
            for (int np=0; np<2; np++){
                ldsm4t(bfr[np], bbase +
                      (unsigned)(((ks*16 + (lane&15))*17 + wn*4 + np*2 + (lane>>4))*16));
            }
            #pragma unroll
            for (int mf=0; mf<4; mf++){
                #pragma unroll
                for (int np=0; np<2; np++){
                    mma_bf16(acc[mf][np*2  ], afr[mf], bfr[np]);
                    mma_bf16(acc[mf][np*2+1], afr[mf], bfr[np]+2);
                }
            }
        }

        if (kt+2 < NKT){
            int st = (kt+2)%3;
            int ktile = kt+2;
            unsigned ab = smem_u + st*SSTAGE;
            unsigned bb2 = ab + 10240;
            #pragma unroll
            for (int i=0;i<2;i++){
                int id = tid + i*256;
                int m = id>>2, c = id&3;
                cpa16(ab + (unsigned)((m*5 + c)*16),
                      Ag + (size_t)(row0+m)*128 + ktile*4 + c);
                int k = id>>4, c2 = id&15;
                cpa16(bb2 + (unsigned)((k*17 + c2)*16),
                      Bg + (size_t)(ktile*32+k)*ldn4 + col4 + c2);
            }
        }
        cpa_commit();
        buf = (buf+1)%3;
    }

    // ---- epilogue (same accumulator layout as before)
    if (MODE == 2){
        #pragma unroll
        for (int mf=0; mf<4; mf++)
            #pragma unroll
            for (int nf=0; nf<4; nf++)
                #pragma unroll
                for (int e=0; e<4; e++){
                    int r = row0 + wm*64 + mf*16 + (lane>>2) + ((e>=2)?8:0);
                    int c = col0 + wn*32 + nf*8 + 2*(lane&3) + (e&1);
                    Cout[(size_t)r*DM + c] = acc[mf][nf][e] + b1[c] + g_ln[(size_t)r*DM + c];
                }
    } else {
        #pragma unroll
        for (int mf=0; mf<4; mf++){
            #pragma unroll
            for (int nf=0; nf<4; nf++){
                int c = col0 + wn*32 + nf*8 + 2*(lane&3);
                #pragma unroll
                for (int half=0; half<2; half++){
                    int r = row0 + wm*64 + mf*16 + (lane>>2) + half*8;
                    int bb = r >> 10, sIdx = r & 1023;
                    float v0 = acc[mf][nf][half*2+0];
                    float v1 = acc[mf][nf][half*2+1];
                    if (c < 1024){
                        unsigned u = packbf((v0 + b1[c])*0.125f, (v1 + b1[c+1])*0.125f);
                        int h = c>>6, d = c&63;
                        g_qu[(((size_t)(bb*NH+h))*SQL + sIdx)*32 + (d>>1)] = u;
                    } else if (c < 2048){
                        int cc = c-1024;
                        unsigned u = packbf(v0 + b2[cc], v1 + b2[cc+1]);
                        int h = cc>>6, d = cc&63;
                        g_ku[(((size_t)(bb*NH+h))*SQL + sIdx)*32 + (d>>1)] = u;
                    } else {
                        int cc = c-2048;
                        unsigned u = packbf(v0 + b2[cc+1024], v1 + b2[cc+1025]);
                        int h = cc>>6, d = cc&63;
                        g_vu[(((size_t)(bb*NH+h))*SQL + sIdx)*32 + (d>>1)] = u;
                    }
                }
            }
        }
    }
}

// ---------------------------------------------------------------------------
// bf16 tensor-core flash attention (round-5 kernel; output now bf16 to g_aob).
// ---------------------------------------------------------------------------
#define ATSTR 36
#define ATT_KS_U (64*ATSTR)
#define ATT_VS_U (64*ATSTR)
#define ATT_PW_U (128*ATSTR)
#define ATT_SMEM ((ATT_KS_U + ATT_VS_U + ATT_PW_U)*4)

__global__ __launch_bounds__(256) void attn_bf(const int* __restrict__ lens)
{
    extern __shared__ unsigned sm[];
    unsigned* Ks = sm;
    unsigned* Vs = sm + ATT_KS_U;
    unsigned* Pw = sm + ATT_KS_U + ATT_VS_U;

    int bh = blockIdx.x;
    int qb = blockIdx.y;
    int b  = bh >> 4;
    int h  = bh & 15;
    int tid  = threadIdx.x;
    int lane = tid & 31;
    int w    = tid >> 5;
    int q0   = qb*128;
    int sub  = lane >> 3;
    int rr   = lane & 7;

    const uint4* qg = reinterpret_cast<const uint4*>(g_qu + ((size_t)bh*SQL + q0)*32);
    const uint4* kg = reinterpret_cast<const uint4*>(g_ku + (size_t)bh*SQL*32);
    const uint4* vg = reinterpret_cast<const uint4*>(g_vu + (size_t)bh*SQL*32);

    #pragma unroll
    for (int i=0;i<4;i++){
        int id = tid + i*256;
        int row = id>>3, u4 = id&7;
        *reinterpret_cast<uint4*>(&Pw[row*ATSTR + u4*4]) = qg[row*8 + u4];
    }
    __syncthreads();

    unsigned aQ[4][4];
    {
        unsigned abase = s2u(Pw) + (unsigned)(((w*16 + (sub&1)*8 + rr)*ATSTR + (sub>>1)*4)*4);
        #pragma unroll
        for (int ks=0; ks<4; ks++) ldsm4(aQ[ks], abase + ks*8*4);
    }

    int qrow0 = q0 + w*16 + (lane>>2);
    int qrow1 = qrow0 + 8;
    int lr0   = w*16 + (lane>>2);

    float Oacc[8][4];
    #pragma unroll
    for (int i=0;i<8;i++)
        #pragma unroll
        for (int e=0;e<4;e++) Oacc[i][e]=0.f;
    float mi0=-1e30f, mi1=-1e30f, li0=0.f, li1=0.f;

    int len  = lens[b];
    int kmax = min(q0+127, len-1);
    int nkb  = (kmax>>6) + 1;

    unsigned ks_u = s2u(Ks);
    unsigned vs_u = s2u(Vs);
    unsigned pw_u = s2u(Pw);

    for (int kb=0; kb<nkb; kb++){
        int k0 = kb*64;
        __syncthreads();
        #pragma unroll
        for (int i=0;i<2;i++){
            int id = tid + i*256;
            int kr = id>>3, u4 = id&7;
            *reinterpret_cast<uint4*>(&Ks[kr*ATSTR + u4*4]) = kg[(size_t)(k0+kr)*8 + u4];
            *reinterpret_cast<uint4*>(&Vs[kr*ATSTR + u4*4]) = vg[(size_t)(k0+kr)*8 + u4];
        }
        __syncthreads();

        float sc[8][4];
        #pragma unroll
        for (int nf=0; nf<8; nf++){
            sc[nf][0]=0.f; sc[nf][1]=0.f; sc[nf][2]=0.f; sc[nf][3]=0.f;
            unsigned kbase_a = ks_u + (unsigned)(((nf*8 + rr)*ATSTR + sub*4)*4);
            #pragma unroll
            for (int ksp=0; ksp<2; ksp++){
                unsigned bb4[4];
                ldsm4(bb4, kbase_a + ksp*16*4);
                mma_bf16(sc[nf], aQ[2*ksp  ], bb4);
                mma_bf16(sc[nf], aQ[2*ksp+1], bb4+2);
            }
        }

        #pragma unroll
        for (int nf=0; nf<8; nf++){
            int jc = k0 + nf*8 + 2*(lane&3);
            #pragma unroll
            for (int e=0; e<4; e++){
                int j   = jc + (e&1);
                int row = (e>=2) ? qrow1 : qrow0;
                sc[nf][e] = (j<=row && j<len) ? sc[nf][e] : -1e30f;
            }
        }

        float rmax0=-1e30f, rmax1=-1e30f;
        #pragma unroll
        for (int nf=0; nf<8; nf++){
            rmax0 = fmaxf(rmax0, fmaxf(sc[nf][0], sc[nf][1]));
            rmax1 = fmaxf(rmax1, fmaxf(sc[nf][2], sc[nf][3]));
        }
        rmax0 = fmaxf(rmax0, __shfl_xor_sync(0xffffffffu, rmax0, 1));
        rmax0 = fmaxf(rmax0, __shfl_xor_sync(0xffffffffu, rmax0, 2));
        rmax1 = fmaxf(rmax1, __shfl_xor_sync(0xffffffffu, rmax1, 1));
        rmax1 = fmaxf(rmax1, __shfl_xor_sync(0xffffffffu, rmax1, 2));

        float mn0 = fmaxf(mi0, rmax0);
        float mn1 = fmaxf(mi1, rmax1);
        float corr0 = __expf(mi0 - mn0);
        float corr1 = __expf(mi1 - mn1);
        mi0 = mn0; mi1 = mn1;

        float rs0=0.f, rs1=0.f;
        #pragma unroll
        for (int nf=0; nf<8; nf++){
            sc[nf][0] = __expf(sc[nf][0]-mn0);
            sc[nf][1] = __expf(sc[nf][1]-mn0);
            sc[nf][2] = __expf(sc[nf][2]-mn1);
            sc[nf][3] = __expf(sc[nf][3]-mn1);
            rs0 += sc[nf][0]+sc[nf][1];
            rs1 += sc[nf][2]+sc[nf][3];
        }
        rs0 += __shfl_xor_sync(0xffffffffu, rs0, 1);
        rs0 += __shfl_xor_sync(0xffffffffu, rs0, 2);
        rs1 += __shfl_xor_sync(0xffffffffu, rs1, 1);
        rs1 += __shfl_xor_sync(0xffffffffu, rs1, 2);
        li0 = li0*corr0 + rs0;
        li1 = li1*corr1 + rs1;

        #pragma unroll
        for (int nf=0; nf<8; nf++){
            Oacc[nf][0]*=corr0; Oacc[nf][1]*=corr0;
            Oacc[nf][2]*=corr1; Oacc[nf][3]*=corr1;
        }

        #pragma unroll
        for (int nf=0; nf<8; nf++){
            Pw[ lr0   *ATSTR + nf*4 + (lane&3)] = packbf(sc[nf][0], sc[nf][1]);
            Pw[(lr0+8)*ATSTR + nf*4 + (lane&3)] = packbf(sc[nf][2], sc[nf][3]);
        }
        __syncwarp();

        #pragma unroll
        for (int ks=0; ks<4; ks++){
            unsigned aP[4];
            ldsm4(aP, pw_u + (unsigned)(((w*16 + (sub&1)*8 + rr)*ATSTR + ks*8 + (sub>>1)*4)*4));
            unsigned vrow = vs_u + (unsigned)(((ks*16 + (sub&1)*8 + rr)*ATSTR + (sub>>1)*4)*4);
            #pragma unroll
            for (int dfp=0; dfp<4; dfp++){
                unsigned bb4[4];
                ldsm4t(bb4, vrow + dfp*8*4);
                mma_bf16(Oacc[2*dfp  ], aP, bb4);
                mma_bf16(Oacc[2*dfp+1], aP, bb4+2);
            }
        }
    }

    float inv0 = 1.f/li0, inv1 = 1.f/li1;
    unsigned* o0 = g_aob + ((size_t)(b*SQL + qrow0))*512 + h*32;
    unsigned* o1 = g_aob + ((size_t)(b*SQL + qrow1))*512 + h*32;
    #pragma unroll
    for (int df=0; df<8; df++){
        o0[df*4 + (lane&3)] = packbf(Oacc[df][0]*inv0, Oacc[df][1]*inv0);
        o1[df*4 + (lane&3)] = packbf(Oacc[df][2]*inv1, Oacc[df][3]*inv1);
    }
}

// ---------------------------------------------------------------------------
extern "C" void kernel_launch(void* const* d_in, const int* in_sizes, int n_in,
                              void* d_out, int out_size)
{
    const float* x     = (const float*)d_in[0];
    const int*   lens  = (const int*)  d_in[2];
    const float* Wq    = (const float*)d_in[3];
    const float* bq    = (const float*)d_in[4];
    const float* Wkv   = (const float*)d_in[5];
    const float* bkv   = (const float*)d_in[6];
    const float* Wo    = (const float*)d_in[7];
    const float* bo    = (const float*)d_in[8];
    const float* gamma = (const float*)d_in[9];
    const float* beta  = (const float*)d_in[10];
    float* out = (float*)d_out;

    cudaFuncSetAttribute(gemm_cp<0>, cudaFuncAttributeMaxDynamicSharedMemorySize, GEMM_SMEM);
    cudaFuncSetAttribute(gemm_cp<2>, cudaFuncAttributeMaxDynamicSharedMemorySize, GEMM_SMEM);
    cudaFuncSetAttribute(attn_bf,    cudaFuncAttributeMaxDynamicSharedMemorySize, ATT_SMEM);

    wconv2    <<<4096, 256>>>(Wq, Wkv, Wo);
    ln_kernel <<<NTOK, 256>>>(x, gamma, beta);
    gemm_cp<0><<<dim3(24,64), 256, GEMM_SMEM>>>(bq, bkv, nullptr);
    attn_bf   <<<dim3(128,8), 256, ATT_SMEM>>>(lens);
    gemm_cp<2><<<dim3(8, 64), 256, GEMM_SMEM>>>(bo, nullptr, out);
}

// round 7
// speedup vs baseline: 7.0302x; 1.0071x over previous
#include <cuda_runtime.h>
#include <cuda_bf16.h>
#include <math.h>

#define NB 8
#define SQL 1024
#define DM 1024
#define NH 16
#define HD 64
#define NTOK (NB*SQL)

// Q pre-scale: 1/sqrt(64) * log2(e)  (softmax done in base-2)
#define QSCL 0.1803368801111244f

// Scratch (no allocations allowed) — __device__ globals.
__device__ float    g_ln [NTOK*DM];         // LayerNorm(x) fp32, residual
__device__ unsigned g_lnb[NTOK*512];        // LayerNorm(x) bf16x2 (GEMM A)
__device__ unsigned g_qu [NB*NH*SQL*32];    // Q bf16x2, [b,h,s,d/2], pre-scaled QSCL
__device__ unsigned g_ku [NB*NH*SQL*32];    // K bf16x2
__device__ unsigned g_vu [NB*NH*SQL*32];    // V bf16x2
__device__ unsigned g_aob[NTOK*512];        // attention out bf16x2 (GEMM A)
__device__ unsigned g_wqkv[1024*1536];      // [Wq|Wkv] bf16x2, [k][n/2], n=3072
__device__ unsigned g_wob [1024*512];       // Wo bf16x2, [k][n/2], n=1024

__device__ __forceinline__ unsigned packbf(float lo, float hi){
    __nv_bfloat162 h = __floats2bfloat162_rn(lo, hi);
    return *reinterpret_cast<unsigned*>(&h);
}
__device__ __forceinline__ unsigned s2u(const void* p){
    return (unsigned)__cvta_generic_to_shared(p);
}
__device__ __forceinline__ float ex2f(float x){
    float y; asm("ex2.approx.ftz.f32 %0, %1;" : "=f"(y) : "f"(x)); return y;
}
__device__ __forceinline__ void mma_bf16(float* c, const unsigned* a, const unsigned* b){
    asm volatile(
        "mma.sync.aligned.m16n8k16.row.col.f32.bf16.bf16.f32 "
        "{%0,%1,%2,%3}, {%4,%5,%6,%7}, {%8,%9}, {%0,%1,%2,%3};\n"
        : "+f"(c[0]), "+f"(c[1]), "+f"(c[2]), "+f"(c[3])
        : "r"(a[0]), "r"(a[1]), "r"(a[2]), "r"(a[3]), "r"(b[0]), "r"(b[1]));
}
__device__ __forceinline__ void ldsm4(unsigned* r, unsigned addr){
    asm volatile("ldmatrix.sync.aligned.m8n8.x4.shared.b16 {%0,%1,%2,%3}, [%4];"
        : "=r"(r[0]), "=r"(r[1]), "=r"(r[2]), "=r"(r[3]) : "r"(addr));
}
__device__ __forceinline__ void ldsm4t(unsigned* r, unsigned addr){
    asm volatile("ldmatrix.sync.aligned.m8n8.x4.trans.shared.b16 {%0,%1,%2,%3}, [%4];"
        : "=r"(r[0]), "=r"(r[1]), "=r"(r[2]), "=r"(r[3]) : "r"(addr));
}
__device__ __forceinline__ void cpa16(unsigned saddr, const void* g){
    asm volatile("cp.async.cg.shared.global [%0], [%1], 16;" :: "r"(saddr), "l"(g) : "memory");
}
__device__ __forceinline__ void cpa_commit(){
    asm volatile("cp.async.commit_group;" ::: "memory");
}
template<int N> __device__ __forceinline__ void cpa_wait(){
    asm volatile("cp.async.wait_group %0;" :: "n"(N) : "memory");
}

// ---------------------------------------------------------------------------
// Fused prep: blocks 0..8191 do LayerNorm rows; blocks 8192..12287 convert
// weights fp32 -> bf16x2.
// ---------------------------------------------------------------------------
__global__ __launch_bounds__(256) void prep_kernel(const float* __restrict__ x,
                                                   const float* __restrict__ gamma,
                                                   const float* __restrict__ beta,
                                                   const float* __restrict__ Wq,
                                                   const float* __restrict__ Wkv,
                                                   const float* __restrict__ Wo)
{
    int tid = threadIdx.x;
    if (blockIdx.x >= NTOK){
        int id = (blockIdx.x - NTOK)*256 + tid;     // 0 .. 1048575, 4 elems each
        if (id < 786432){                           // qkv region: 1024 x 3072
            int e = id*4;
            int k = e / 3072, n = e % 3072;
            float4 v;
            if (n < 1024) v = *reinterpret_cast<const float4*>(Wq  + (size_t)k*1024 + n);
            else          v = *reinterpret_cast<const float4*>(Wkv + (size_t)k*2048 + (n-1024));
            uint2 u = { packbf(v.x, v.y), packbf(v.z, v.w) };
            *reinterpret_cast<uint2*>(&g_wqkv[(size_t)k*1536 + (n>>1)]) = u;
        } else {                                    // wo region: 1024 x 1024
            int e = (id - 786432)*4;
            float4 v = *reinterpret_cast<const float4*>(Wo + e);
            uint2 u = { packbf(v.x, v.y), packbf(v.z, v.w) };
            *reinterpret_cast<uint2*>(&g_wob[e>>1]) = u;
        }
        return;
    }

    int row = blockIdx.x;
    float4 v = reinterpret_cast<const float4*>(x + (size_t)row*DM)[tid];
    float s  = v.x+v.y+v.z+v.w;
    float ss = v.x*v.x+v.y*v.y+v.z*v.z+v.w*v.w;
    #pragma unroll
    for (int o=16;o;o>>=1){
        s  += __shfl_xor_sync(0xffffffffu, s,  o);
        ss += __shfl_xor_sync(0xffffffffu, ss, o);
    }
    __shared__ float ws[8], wss[8];
    int wid = tid>>5, lid = tid&31;
    if (lid==0){ ws[wid]=s; wss[wid]=ss; }
    __syncthreads();
    if (tid==0){
        float a=0.f,c=0.f;
        #pragma unroll
        for (int i=0;i<8;i++){ a+=ws[i]; c+=wss[i]; }
        ws[0]=a; wss[0]=c;
    }
    __syncthreads();
    float mean = ws[0]*(1.0f/DM);
    float var  = wss[0]*(1.0f/DM) - mean*mean;
    float rstd = rsqrtf(var + 1e-3f);
    float4 g  = reinterpret_cast<const float4*>(gamma)[tid];
    float4 bt = reinterpret_cast<const float4*>(beta)[tid];
    float4 o;
    o.x = (v.x-mean)*rstd*g.x + bt.x;
    o.y = (v.y-mean)*rstd*g.y + bt.y;
    o.z = (v.z-mean)*rstd*g.z + bt.z;
    o.w = (v.w-mean)*rstd*g.w + bt.w;
    reinterpret_cast<float4*>(g_ln + (size_t)row*DM)[tid] = o;
    uint2 u = { packbf(o.x, o.y), packbf(o.z, o.w) };
    *reinterpret_cast<uint2*>(&g_lnb[(size_t)row*512 + tid*2]) = u;
}

// ---------------------------------------------------------------------------
// bf16 pipelined GEMM: C[8192,N] = A[8192,1024] @ W[1024,N], all bf16 in gmem.
// 128x128x32 tiles, 256 thr / 8 warps (2x4), warp tile 64x32, m16n8k16.
// cp.async 3-stage pipeline (prefetch issued BEFORE compute) + ldmatrix.
// Smem chunk layouts (16B units): A: m*5 + k/8 (pad-5); B: k*17 + n/8 (pad-17).
// MODE 0: A=g_lnb, B=g_wqkv(ldn 3072) -> scatter Q(*QSCL)/K/V bf16.
// MODE 2: A=g_aob, B=g_wob(ldn 1024)  -> out = acc + bias + residual (fp32).
// ---------------------------------------------------------------------------
#define SSTAGE 18944                 // bytes per stage: A 10240 + B 8704
#define GEMM_SMEM (3*SSTAGE)         // 56832

template<int MODE>
__global__ __launch_bounds__(256) void gemm_cp(const float* __restrict__ b1,
                                               const float* __restrict__ b2,
                                               float* __restrict__ Cout)
{
    extern __shared__ unsigned char smem_raw[];
    unsigned smem_u = s2u(smem_raw);

    const uint4* Ag = reinterpret_cast<const uint4*>((MODE==2) ? g_aob : g_lnb);
    const uint4* Bg = reinterpret_cast<const uint4*>((MODE==2) ? g_wob : g_wqkv);
    const int ldn4  = (MODE==2) ? 128 : 384;    // uint4 per weight row

    int tid  = threadIdx.x;
    int lane = tid & 31;
    int warp = tid >> 5;
    int wm = warp >> 2, wn = warp & 3;
    int row0 = blockIdx.y * 128;
    int col0 = blockIdx.x * 128;
    int col4 = col0 >> 3;

    float acc[4][4][4];
    #pragma unroll
    for (int i=0;i<4;i++)
        #pragma unroll
        for (int j=0;j<4;j++)
            #pragma unroll
            for (int e=0;e<4;e++) acc[i][j][e]=0.f;

    const int NKT = 32;

    // ---- prologue: stages 0,1
    #pragma unroll
    for (int st=0; st<2; st++){
        unsigned ab = smem_u + st*SSTAGE;
        unsigned bb = ab + 10240;
        #pragma unroll
        for (int i=0;i<2;i++){
            int id = tid + i*256;
            int m = id>>2, c = id&3;
            cpa16(ab + (unsigned)((m*5 + c)*16),
                  Ag + (size_t)(row0+m)*128 + st*4 + c);
            int k = id>>4, c2 = id&15;
            cpa16(bb + (unsigned)((k*17 + c2)*16),
                  Bg + (size_t)(st*32+k)*ldn4 + col4 + c2);
        }
        cpa_commit();
    }

    int buf = 0;
    for (int kt = 0; kt < NKT; kt++){
        cpa_wait<1>();
        __syncthreads();

        // prefetch kt+2 BEFORE compute (its stage was drained last iteration)
        if (kt+2 < NKT){
            int st = (kt+2)%3;
            int ktile = kt+2;
            unsigned ab = smem_u + st*SSTAGE;
            unsigned bb2 = ab + 10240;
            #pragma unroll
            for (int i=0;i<2;i++){
                int id = tid + i*256;
                int m = id>>2, c = id&3;
                cpa16(ab + (unsigned)((m*5 + c)*16),
                      Ag + (size_t)(row0+m)*128 + ktile*4 + c);
                int k = id>>4, c2 = id&15;
                cpa16(bb2 + (unsigned)((k*17 + c2)*16),
                      Bg + (size_t)(ktile*32+k)*ldn4 + col4 + c2);
            }
        }
        cpa_commit();

        unsigned abase = smem_u + buf*SSTAGE;
        unsigned bbase = abase + 10240;
        #pragma unroll
        for (int ks=0; ks<2; ks++){
            unsigned afr[4][4], bfr[2][4];
            #pragma unroll
            for (int mf=0; mf<4; mf++){
                int m0 = wm*64 + mf*16;
                ldsm4(afr[mf], abase +
                      (unsigned)((((m0 + (lane&15))*5) + ks*2 + (lane>>4))*16));
            }
            #pragma unroll
            for (int np=0; np<2; np++){
                ldsm4t(bfr[np], bbase +
                      (unsigned)(((ks*16 + (lane&15))*17 + wn*4 + np*2 + (lane>>4))*16));
            }
            #pragma unroll
            for (int mf=0; mf<4; mf++){
                #pragma unroll
                for (int np=0; np<2; np++){
                    mma_bf16(acc[mf][np*2  ], afr[mf], bfr[np]);
                    mma_bf16(acc[mf][np*2+1], afr[mf], bfr[np]+2);
                }
            }
        }
        buf = (buf+1)%3;
    }

    // ---- epilogue
    if (MODE == 2){
        #pragma unroll
        for (int mf=0; mf<4; mf++)
            #pragma unroll
            for (int nf=0; nf<4; nf++)
                #pragma unroll
                for (int e=0; e<4; e++){
                    int r = row0 + wm*64 + mf*16 + (lane>>2) + ((e>=2)?8:0);
                    int c = col0 + wn*32 + nf*8 + 2*(lane&3) + (e&1);
                    Cout[(size_t)r*DM + c] = acc[mf][nf][e] + b1[c] + g_ln[(size_t)r*DM + c];
                }
    } else {
        #pragma unroll
        for (int mf=0; mf<4; mf++){
            #pragma unroll
            for (int nf=0; nf<4; nf++){
                int c = col0 + wn*32 + nf*8 + 2*(lane&3);
                #pragma unroll
                for (int half=0; half<2; half++){
                    int r = row0 + wm*64 + mf*16 + (lane>>2) + half*8;
                    int bb = r >> 10, sIdx = r & 1023;
                    float v0 = acc[mf][nf][half*2+0];
                    float v1 = acc[mf][nf][half*2+1];
                    if (c < 1024){
                        unsigned u = packbf((v0 + b1[c])*QSCL, (v1 + b1[c+1])*QSCL);
                        int h = c>>6, d = c&63;
                        g_qu[(((size_t)(bb*NH+h))*SQL + sIdx)*32 + (d>>1)] = u;
                    } else if (c < 2048){
                        int cc = c-1024;
                        unsigned u = packbf(v0 + b2[cc], v1 + b2[cc+1]);
                        int h = cc>>6, d = cc&63;
                        g_ku[(((size_t)(bb*NH+h))*SQL + sIdx)*32 + (d>>1)] = u;
                    } else {
                        int cc = c-2048;
                        unsigned u = packbf(v0 + b2[cc+1024], v1 + b2[cc+1025]);
                        int h = cc>>6, d = cc&63;
                        g_vu[(((size_t)(bb*NH+h))*SQL + sIdx)*32 + (d>>1)] = u;
                    }
                }
            }
        }
    }
}

// ---------------------------------------------------------------------------
// bf16 flash attention, v3:
//  - Q fragments loaded directly from gmem (no staging)
//  - P kept in registers (C-frag of S == A-frag of PV) — no smem round trip
//  - K/V double-buffered via cp.async (2 stages)
//  - tile-level mask skip; softmax in base-2 (Q pre-scaled by log2e/8)
//  - heavy (high-qb) blocks scheduled first
// ---------------------------------------------------------------------------
#define ATSTR 36
#define TILE_KV (64*ATSTR)                 // uints per K or V tile
#define ATT_SMEM (4*TILE_KV*4)             // 2 stages * (K+V) = 36864 B

__global__ __launch_bounds__(256) void attn_bf(const int* __restrict__ lens)
{
    extern __shared__ unsigned sm[];
    unsigned smem_u = s2u(sm);

    int bh = blockIdx.x;
    int qb = (int)(gridDim.y - 1 - blockIdx.y);    // heavy tiles first
    int b  = bh >> 4;
    int h  = bh & 15;
    int tid  = threadIdx.x;
    int lane = tid & 31;
    int w    = tid >> 5;
    int q0   = qb*128;
    int sub  = lane >> 3;
    int rr   = lane & 7;

    const uint4* kg = reinterpret_cast<const uint4*>(g_ku + (size_t)bh*SQL*32);
    const uint4* vg = reinterpret_cast<const uint4*>(g_vu + (size_t)bh*SQL*32);

    int len  = lens[b];
    int kmax = min(q0+127, len-1);
    int nkb  = (kmax>>6) + 1;

    // ---- prologue: issue K/V tile 0 into stage 0
    {
        unsigned kb_s = smem_u;
        unsigned vb_s = smem_u + TILE_KV*4;
        #pragma unroll
        for (int i=0;i<2;i++){
            int id = tid + i*256;
            int r = id>>3, c = id&7;
            cpa16(kb_s + (unsigned)((r*ATSTR + c*4)*4), kg + (size_t)r*8 + c);
            cpa16(vb_s + (unsigned)((r*ATSTR + c*4)*4), vg + (size_t)r*8 + c);
        }
        cpa_commit();
    }

    int qrow0 = q0 + w*16 + (lane>>2);
    int qrow1 = qrow0 + 8;

    // ---- Q fragments straight from gmem (one uint each)
    unsigned aQ[4][4];
    {
        const unsigned* q0p = g_qu + ((size_t)bh*SQL + qrow0)*32;
        const unsigned* q1p = g_qu + ((size_t)bh*SQL + qrow1)*32;
        #pragma unroll
        for (int ks=0; ks<4; ks++){
            aQ[ks][0] = q0p[ks*8 +     (lane&3)];
            aQ[ks][1] = q1p[ks*8 +     (lane&3)];
            aQ[ks][2] = q0p[ks*8 + 4 + (lane&3)];
            aQ[ks][3] = q1p[ks*8 + 4 + (lane&3)];
        }
    }

    float Oacc[8][4];
    #pragma unroll
    for (int i=0;i<8;i++)
        #pragma unroll
        for (int e=0;e<4;e++) Oacc[i][e]=0.f;
    float mi0=-1e30f, mi1=-1e30f, li0=0.f, li1=0.f;

    int buf = 0;
    for (int kb=0; kb<nkb; kb++){
        int k0 = kb*64;
        __syncthreads();            // all warps done reading stage buf^1
        if (kb+1 < nkb){
            int kn = (kb+1)*64;
            unsigned kb_s = smem_u + (unsigned)((buf^1)*(2*TILE_KV*4));
            unsigned vb_s = kb_s + TILE_KV*4;
            #pragma unroll
            for (int i=0;i<2;i++){
                int id = tid + i*256;
                int r = id>>3, c = id&7;
                cpa16(kb_s + (unsigned)((r*ATSTR + c*4)*4), kg + (size_t)(kn+r)*8 + c);
                cpa16(vb_s + (unsigned)((r*ATSTR + c*4)*4), vg + (size_t)(kn+r)*8 + c);
            }
        }
        cpa_commit();
        cpa_wait<1>();
        __syncthreads();            // stage buf visible to all warps

        unsigned kstage = smem_u + (unsigned)(buf*(2*TILE_KV*4));
        unsigned vstage = kstage + TILE_KV*4;

        // ---- S = Q K^T (log2-domain scores; Q pre-scaled)
        float sc[8][4];
        #pragma unroll
        for (int nf=0; nf<8; nf++){
            sc[nf][0]=0.f; sc[nf][1]=0.f; sc[nf][2]=0.f; sc[nf][3]=0.f;
            unsigned kbase_a = kstage + (unsigned)(((nf*8 + rr)*ATSTR + sub*4)*4);
            #pragma unroll
            for (int ksp=0; ksp<2; ksp++){
                unsigned bb4[4];
                ldsm4(bb4, kbase_a + ksp*16*4);
                mma_bf16(sc[nf], aQ[2*ksp  ], bb4);
                mma_bf16(sc[nf], aQ[2*ksp+1], bb4+2);
            }
        }

        // ---- mask (skipped for fully-interior tiles)
        if (k0+63 > q0 + w*16 || k0+63 >= len){
            #pragma unroll
            for (int nf=0; nf<8; nf++){
                int jc = k0 + nf*8 + 2*(lane&3);
                #pragma unroll
                for (int e=0; e<4; e++){
                    int j   = jc + (e&1);
                    int row = (e>=2) ? qrow1 : qrow0;
                    sc[nf][e] = (j<=row && j<len) ? sc[nf][e] : -1e30f;
                }
            }
        }

        // ---- online softmax (base-2)
        float rmax0=-1e30f, rmax1=-1e30f;
        #pragma unroll
        for (int nf=0; nf<8; nf++){
            rmax0 = fmaxf(rmax0, fmaxf(sc[nf][0], sc[nf][1]));
            rmax1 = fmaxf(rmax1, fmaxf(sc[nf][2], sc[nf][3]));
        }
        rmax0 = fmaxf(rmax0, __shfl_xor_sync(0xffffffffu, rmax0, 1));
        rmax0 = fmaxf(rmax0, __shfl_xor_sync(0xffffffffu, rmax0, 2));
        rmax1 = fmaxf(rmax1, __shfl_xor_sync(0xffffffffu, rmax1, 1));
        rmax1 = fmaxf(rmax1, __shfl_xor_sync(0xffffffffu, rmax1, 2));

        float mn0 = fmaxf(mi0, rmax0);
        float mn1 = fmaxf(mi1, rmax1);
        float corr0 = ex2f(mi0 - mn0);
        float corr1 = ex2f(mi1 - mn1);
        mi0 = mn0; mi1 = mn1;

        float rs0=0.f, rs1=0.f;
        #pragma unroll
        for (int nf=0; nf<8; nf++){
            sc[nf][0] = ex2f(sc[nf][0]-mn0);
            sc[nf][1] = ex2f(sc[nf][1]-mn0);
            sc[nf][2] = ex2f(sc[nf][2]-mn1);
            sc[nf][3] = ex2f(sc[nf][3]-mn1);
            rs0 += sc[nf][0]+sc[nf][1];
            rs1 += sc[nf][2]+sc[nf][3];
        }
        rs0 += __shfl_xor_sync(0xffffffffu, rs0, 1);
        rs0 += __shfl_xor_sync(0xffffffffu, rs0, 2);
        rs1 += __shfl_xor_sync(0xffffffffu, rs1, 1);
        rs1 += __shfl_xor_sync(0xffffffffu, rs1, 2);
        li0 = li0*corr0 + rs0;
        li1 = li1*corr1 + rs1;

        #pragma unroll
        for (int nf=0; nf<8; nf++){
            Oacc[nf][0]*=corr0; Oacc[nf][1]*=corr0;
            Oacc[nf][2]*=corr1; Oacc[nf][3]*=corr1;
        }

        // ---- O += P V : P stays in registers (C-frag == A-frag layout)
        #pragma unroll
        for (int ks=0; ks<4; ks++){
            unsigned aP[4];
            aP[0] = packbf(sc[2*ks  ][0], sc[2*ks  ][1]);
            aP[1] = packbf(sc[2*ks  ][2], sc[2*ks  ][3]);
            aP[2] = packbf(sc[2*ks+1][0], sc[2*ks+1][1]);
            aP[3] = packbf(sc[2*ks+1][2], sc[2*ks+1][3]);
            unsigned vrow = vstage + (unsigned)(((ks*16 + (sub&1)*8 + rr)*ATSTR + (sub>>1)*4)*4);
            #pragma unroll
            for (int dfp=0; dfp<4; dfp++){
                unsigned bb4[4];
                ldsm4t(bb4, vrow + dfp*8*4);
                mma_bf16(Oacc[2*dfp  ], aP, bb4);
                mma_bf16(Oacc[2*dfp+1], aP, bb4+2);
            }
        }
        buf ^= 1;
    }

    // ---- write O as bf16x2
    float inv0 = 1.f/li0, inv1 = 1.f/li1;
    unsigned* o0 = g_aob + ((size_t)(b*SQL + qrow0))*512 + h*32;
    unsigned* o1 = g_aob + ((size_t)(b*SQL + qrow1))*512 + h*32;
    #pragma unroll
    for (int df=0; df<8; df++){
        o0[df*4 + (lane&3)] = packbf(Oacc[df][0]*inv0, Oacc[df][1]*inv0);
        o1[df*4 + (lane&3)] = packbf(Oacc[df][2]*inv1, Oacc[df][3]*inv1);
    }
}

// ---------------------------------------------------------------------------
extern "C" void kernel_launch(void* const* d_in, const int* in_sizes, int n_in,
                              void* d_out, int out_size)
{
    const float* x     = (const float*)d_in[0];
    const int*   lens  = (const int*)  d_in[2];
    const float* Wq    = (const float*)d_in[3];
    const float* bq    = (const float*)d_in[4];
    const float* Wkv   = (const float*)d_in[5];
    const float* bkv   = (const float*)d_in[6];
    const float* Wo    = (const float*)d_in[7];
    const float* bo    = (const float*)d_in[8];
    const float* gamma = (const float*)d_in[9];
    const float* beta  = (const float*)d_in[10];
    float* out = (float*)d_out;

    cudaFuncSetAttribute(gemm_cp<0>, cudaFuncAttributeMaxDynamicSharedMemorySize, GEMM_SMEM);
    cudaFuncSetAttribute(gemm_cp<2>, cudaFuncAttributeMaxDynamicSharedMemorySize, GEMM_SMEM);
    cudaFuncSetAttribute(attn_bf,    cudaFuncAttributeMaxDynamicSharedMemorySize, ATT_SMEM);

    prep_kernel<<<NTOK + 4096, 256>>>(x, gamma, beta, Wq, Wkv, Wo);
    gemm_cp<0><<<dim3(24,64), 256, GEMM_SMEM>>>(bq, bkv, nullptr);
    attn_bf   <<<dim3(128,8), 256, ATT_SMEM>>>(lens);
    gemm_cp<2><<<dim3(8, 64), 256, GEMM_SMEM>>>(bo, nullptr, out);
}